// round 7
// baseline (speedup 1.0000x reference)
#include <cuda_runtime.h>
#include <cuda_bf16.h>
#include <math_constants.h>
#include <cstdint>

#define BZ   32
#define RVN  16
#define RVL  64
#define H    256
#define NTOK 1024
#define HID  256
#define EPSF 1e-8f
#define NEGV -100000000.0f

// ---------------- scratch ----------------------------------------------------
__device__ __align__(16) float g_invb[BZ * NTOK];
__device__ __align__(16) float g_sb_part[32][BZ][H];
__device__ __align__(16) float g_sb[BZ * H];
__device__ __align__(16) float g_denom[BZ];
__device__ __align__(16) float g_word[BZ * NTOK];
__device__ __align__(16) float g_inva[BZ * NTOK];
__device__ __align__(16) float g_mean[BZ * NTOK];
__device__ __align__(16) float g_max[BZ * NTOK];
__device__ int g_mask_byte;
// bf16 hi/lo split operands (A raw, B pre-scaled by 1/||b||), row-major [tok][256]
__device__ __align__(16) __nv_bfloat16 g_ah[BZ * NTOK * H];
__device__ __align__(16) __nv_bfloat16 g_al[BZ * NTOK * H];
__device__ __align__(16) __nv_bfloat16 g_bh[BZ * NTOK * H];
__device__ __align__(16) __nv_bfloat16 g_bl[BZ * NTOK * H];

__device__ __forceinline__ bool mask_at(const void* m, int i) {
    if (g_mask_byte) return ((const unsigned char*)m)[i] != 0;
    return ((const unsigned int*)m)[i] != 0u;
}
__device__ __forceinline__ float dot4(float4 a, float4 b) {
    return a.x * b.x + a.y * b.y + a.z * b.z + a.w * b.w;
}
__device__ __forceinline__ void cvt4(float4 v, float s,
                                     __nv_bfloat16* hp, __nv_bfloat16* lp) {
    float x0 = v.x * s, x1 = v.y * s, x2 = v.z * s, x3 = v.w * s;
    __nv_bfloat16 h0 = __float2bfloat16(x0), h1 = __float2bfloat16(x1);
    __nv_bfloat16 h2 = __float2bfloat16(x2), h3 = __float2bfloat16(x3);
    __nv_bfloat16 l0 = __float2bfloat16(x0 - __bfloat162float(h0));
    __nv_bfloat16 l1 = __float2bfloat16(x1 - __bfloat162float(h1));
    __nv_bfloat16 l2 = __float2bfloat16(x2 - __bfloat162float(h2));
    __nv_bfloat16 l3 = __float2bfloat16(x3 - __bfloat162float(h3));
    uint2 hu, lu;
    hu.x = (unsigned)__bfloat16_as_ushort(h0) | ((unsigned)__bfloat16_as_ushort(h1) << 16);
    hu.y = (unsigned)__bfloat16_as_ushort(h2) | ((unsigned)__bfloat16_as_ushort(h3) << 16);
    lu.x = (unsigned)__bfloat16_as_ushort(l0) | ((unsigned)__bfloat16_as_ushort(l1) << 16);
    lu.y = (unsigned)__bfloat16_as_ushort(l2) | ((unsigned)__bfloat16_as_ushort(l3) << 16);
    *(uint2*)hp = hu;
    *(uint2*)lp = lu;
}

__device__ __forceinline__ uint32_t smem_u32(const void* p) {
    uint32_t a;
    asm("{ .reg .u64 t; cvta.to.shared.u64 t, %1; cvt.u32.u64 %0, t; }"
        : "=r"(a) : "l"(p));
    return a;
}
__device__ __forceinline__ void cpa16(uint32_t dst, const void* src) {
    asm volatile("cp.async.cg.shared.global [%0], [%1], 16;" :: "r"(dst), "l"(src));
}
__device__ __forceinline__ void ldsm4(uint32_t addr, uint32_t* r) {
    asm volatile("ldmatrix.sync.aligned.m8n8.x4.shared.b16 {%0,%1,%2,%3}, [%4];"
                 : "=r"(r[0]), "=r"(r[1]), "=r"(r[2]), "=r"(r[3]) : "r"(addr));
}
__device__ __forceinline__ void mma16816(float* c, const uint32_t* a,
                                         uint32_t b0, uint32_t b1) {
    asm volatile(
        "mma.sync.aligned.m16n8k16.row.col.f32.bf16.bf16.f32 "
        "{%0,%1,%2,%3}, {%4,%5,%6,%7}, {%8,%9}, {%0,%1,%2,%3};"
        : "+f"(c[0]), "+f"(c[1]), "+f"(c[2]), "+f"(c[3])
        : "r"(a[0]), "r"(a[1]), "r"(a[2]), "r"(a[3]), "r"(b0), "r"(b1));
}

// ---------------- fused mask-width detect + per-batch denom ------------------
__global__ void k_detect_denom(const unsigned char* __restrict__ mbraw,
                               const void* __restrict__ mask_b) {
    __shared__ int mbyte;
    int t = threadIdx.x;  // 1024 threads
    if (t == 0) {
        int cnt = 0;
        for (int i = 0; i < 1024; i++) cnt += mbraw[i * 4 + 1] ? 1 : 0;
        int v = (cnt > 64) ? 1 : 0;
        g_mask_byte = v;
        mbyte = v;
    }
    __syncthreads();
    int b = t >> 5, lane = t & 31;
    int c = 0;
    for (int q = lane; q < NTOK; q += 32) {
        bool m = mbyte ? (((const unsigned char*)mask_b)[b * NTOK + q] != 0)
                       : (((const unsigned int*)mask_b)[b * NTOK + q] != 0u);
        c += m ? 1 : 0;
    }
#pragma unroll
    for (int off = 16; off > 0; off >>= 1)
        c += __shfl_xor_sync(0xffffffffu, c, off);
    if (lane == 0) g_denom[b] = fmaxf((float)c, 1.0f);
}

// ---------------- b prep: invb + bf16 hi/lo of normalized b ------------------
__global__ void k_prep_b(const float* __restrict__ seq_b) {
    int tok  = blockIdx.x * 8 + (threadIdx.x >> 5);
    int lane = threadIdx.x & 31;
    const float4* p = (const float4*)(seq_b + (size_t)tok * H);
    float4 v0 = p[lane], v1 = p[lane + 32];
    float ss = dot4(v0, v0) + dot4(v1, v1);
#pragma unroll
    for (int off = 16; off > 0; off >>= 1)
        ss += __shfl_xor_sync(0xffffffffu, ss, off);
    float ib = 1.0f / (sqrtf(ss) + EPSF);
    if (lane == 0) g_invb[tok] = ib;
    size_t base = (size_t)tok * H;
    cvt4(v0, ib, g_bh + base + lane * 4, g_bl + base + lane * 4);
    cvt4(v1, ib, g_bh + base + 128 + lane * 4, g_bl + base + 128 + lane * 4);
}

// ---------------- masked sums of normalized b --------------------------------
__global__ void k_sb_part(const float* __restrict__ seq_b,
                          const void* __restrict__ mask_b) {
    int b = blockIdx.y, c = blockIdx.x, t = threadIdx.x;
    const float* Bb = seq_b + ((size_t)b * NTOK + c * 32) * H;
    const float* ib = g_invb + b * NTOK + c * 32;
    int mbase = b * NTOK + c * 32;
    float s = 0.f;
#pragma unroll 4
    for (int n = 0; n < 32; n++) {
        float sc = mask_at(mask_b, mbase + n) ? ib[n] : 0.0f;
        s += Bb[(size_t)n * H + t] * sc;
    }
    g_sb_part[c][b][t] = s;
}
__global__ void k_sb_reduce() {
    int b = blockIdx.x, t = threadIdx.x;
    float s = 0.f;
#pragma unroll
    for (int c = 0; c < 32; c++) s += g_sb_part[c][b][t];
    g_sb[b * H + t] = s;
}

// ---------------- a prep: word/inva/mean + bf16 hi/lo of a -------------------
__global__ void k_prep_a(const float* __restrict__ seq_a,
                         const void* __restrict__ mask_a,
                         const float* __restrict__ w_word,
                         const float* __restrict__ b_word) {
    int tok  = blockIdx.x * 8 + (threadIdx.x >> 5);
    int lane = threadIdx.x & 31;
    int b    = tok >> 10;
    const float4* pa = (const float4*)(seq_a + (size_t)tok * H);
    const float4* pw = (const float4*)w_word;
    const float4* ps = (const float4*)(g_sb + b * H);
    float4 a0 = pa[lane], a1 = pa[lane + 32];
    float4 w0 = pw[lane], w1v = pw[lane + 32];
    float4 s0 = ps[lane], s1 = ps[lane + 32];
    float ss = dot4(a0, a0) + dot4(a1, a1);
    float dw = dot4(a0, w0) + dot4(a1, w1v);
    float ds = dot4(a0, s0) + dot4(a1, s1);
#pragma unroll
    for (int off = 16; off > 0; off >>= 1) {
        ss += __shfl_xor_sync(0xffffffffu, ss, off);
        dw += __shfl_xor_sync(0xffffffffu, dw, off);
        ds += __shfl_xor_sync(0xffffffffu, ds, off);
    }
    float inva = 1.0f / (sqrtf(ss) + EPSF);
    if (lane == 0) {
        float ma   = mask_at(mask_a, tok) ? 1.0f : 0.0f;
        g_word[tok] = (dw + b_word[0]) * ma;
        g_inva[tok] = inva;
        g_mean[tok] = inva * ds / g_denom[b];
    }
    size_t base = (size_t)tok * H;
    cvt4(a0, 1.0f, g_ah + base + lane * 4, g_al + base + lane * 4);
    cvt4(a1, 1.0f, g_ah + base + 128 + lane * 4, g_al + base + 128 + lane * 4);
}

// ---------------- HMMA GEMM with row-max epilogue -----------------------------
// BM=64 (A fully K-resident in smem hi/lo = 64KB), 8 n-tiles of 128, K-chunk 64.
// 8 warps = 2 wm x 4 wn; each warp: 32 rows x 32 cols. 3-pass bf16 hi/lo.
// cp.async pipelined B (2 x 32KB buffers). Total smem 128KB.
#define OFF_AL 2048   // uint4 units
#define OFF_B0 4096
#define SMEM_BYTES (8192 * 16)

__global__ __launch_bounds__(256, 1) void k_gemm_max() {
    extern __shared__ __align__(128) unsigned char smraw[];
    const uint32_t smb = smem_u32(smraw);

    const int b   = blockIdx.y;
    const int m0  = blockIdx.x * 64;
    const int tid = threadIdx.x, wid = tid >> 5, lane = tid & 31;
    const int wm = wid & 1, wn = wid >> 1;
    const int g = lane >> 3, ril = lane & 7;

    const uint4* gah = (const uint4*)g_ah + (size_t)(b * NTOK + m0) * 32;
    const uint4* gal = (const uint4*)g_al + (size_t)(b * NTOK + m0) * 32;
    const uint4* gbh = (const uint4*)g_bh + (size_t)b * NTOK * 32;
    const uint4* gbl = (const uint4*)g_bl + (size_t)b * NTOK * 32;

    // A: 64 rows x 32 uint4 (hi at 0, lo at OFF_AL), swizzled
#pragma unroll
    for (int i = 0; i < 8; i++) {
        int idx = tid + i * 256;
        int r = idx >> 5, c = idx & 31, cs = c ^ (r & 7);
        cpa16(smb + (uint32_t)(r * 32 + cs) * 16, gah + r * 32 + c);
        cpa16(smb + (uint32_t)(OFF_AL + r * 32 + cs) * 16, gal + r * 32 + c);
    }
    asm volatile("cp.async.commit_group;" ::: "memory");

    // B chunk loader: n-tile nt (128 rows), k-chunk kc (64 cols) into buf
    auto loadB = [&](int nt, int kc, int buf) {
        uint32_t base = smb + (uint32_t)(OFF_B0 + buf * 2048) * 16;
#pragma unroll
        for (int i = 0; i < 4; i++) {
            int idx = tid + i * 256;
            int n = idx >> 3, c = idx & 7, cs = c ^ (n & 7);
            size_t gi = (size_t)(nt * 128 + n) * 32 + kc * 8 + c;
            cpa16(base + (uint32_t)(n * 8 + cs) * 16, gbh + gi);
            cpa16(base + (uint32_t)(1024 + n * 8 + cs) * 16, gbl + gi);
        }
        asm volatile("cp.async.commit_group;" ::: "memory");
    };
    loadB(0, 0, 0);

    float pm[2][2];
    pm[0][0] = pm[0][1] = pm[1][0] = pm[1][1] = -CUDART_INF_F;
    float acc[2][4][4];

    for (int it = 0; it < 32; it++) {
        int kc = it & 3, buf = it & 1;
        if (it > 0) __syncthreads();  // all reads of buf^1 done before overwrite
        if (it < 31) {
            int nit = it + 1;
            loadB(nit >> 2, nit & 3, buf ^ 1);
            asm volatile("cp.async.wait_group 1;" ::: "memory");
        } else {
            asm volatile("cp.async.wait_group 0;" ::: "memory");
        }
        __syncthreads();

        if (kc == 0) {
#pragma unroll
            for (int mt = 0; mt < 2; mt++)
#pragma unroll
                for (int n = 0; n < 4; n++)
#pragma unroll
                    for (int q = 0; q < 4; q++) acc[mt][n][q] = 0.f;
        }

#pragma unroll
        for (int ks = 0; ks < 4; ks++) {
            uint32_t ah[2][4], al[2][4], bh[2][4], bl[2][4];
#pragma unroll
            for (int mt = 0; mt < 2; mt++) {
                int r = wm * 32 + mt * 16 + ((g & 1) << 3) + ril;
                int c = kc * 8 + ks * 2 + (g >> 1);
                int cs = c ^ (r & 7);
                ldsm4(smb + (uint32_t)(r * 32 + cs) * 16, ah[mt]);
                ldsm4(smb + (uint32_t)(OFF_AL + r * 32 + cs) * 16, al[mt]);
            }
#pragma unroll
            for (int np = 0; np < 2; np++) {
                int r = wn * 32 + np * 16 + ((g & 1) << 3) + ril;
                int c = ks * 2 + (g >> 1);
                int cs = c ^ (r & 7);
                uint32_t base = (uint32_t)(OFF_B0 + buf * 2048 + r * 8 + cs);
                ldsm4(smb + base * 16, bh[np]);
                ldsm4(smb + (base + 1024) * 16, bl[np]);
            }
            // B x4 frags: [0]={n0-7,kLo} [1]={n8-15,kLo} [2]={n0-7,kHi} [3]={n8-15,kHi}
#pragma unroll
            for (int mt = 0; mt < 2; mt++)
#pragma unroll
                for (int np = 0; np < 2; np++)
#pragma unroll
                    for (int sub = 0; sub < 2; sub++) {
                        float* c4 = acc[mt][np * 2 + sub];
                        uint32_t bx0 = bh[np][sub], bx1 = bh[np][sub + 2];
                        uint32_t by0 = bl[np][sub], by1 = bl[np][sub + 2];
                        mma16816(c4, ah[mt], bx0, bx1);
                        mma16816(c4, ah[mt], by0, by1);
                        mma16816(c4, al[mt], bx0, bx1);
                    }
        }

        if (kc == 3) {
#pragma unroll
            for (int mt = 0; mt < 2; mt++)
#pragma unroll
                for (int n = 0; n < 4; n++) {
                    pm[mt][0] = fmaxf(pm[mt][0], fmaxf(acc[mt][n][0], acc[mt][n][1]));
                    pm[mt][1] = fmaxf(pm[mt][1], fmaxf(acc[mt][n][2], acc[mt][n][3]));
                }
        }
    }

    // cross-lane + cross-warp max: 64 rows x 4 wn
    __syncthreads();
    float* mred = (float*)smraw;
#pragma unroll
    for (int mt = 0; mt < 2; mt++)
#pragma unroll
        for (int hf = 0; hf < 2; hf++) {
            float v = pm[mt][hf];
            v = fmaxf(v, __shfl_xor_sync(0xffffffffu, v, 1));
            v = fmaxf(v, __shfl_xor_sync(0xffffffffu, v, 2));
            if ((lane & 3) == 0)
                mred[(wm * 32 + mt * 16 + hf * 8 + (lane >> 2)) * 4 + wn] = v;
        }
    __syncthreads();
    if (tid < 64) {
        float v = fmaxf(fmaxf(mred[tid * 4], mred[tid * 4 + 1]),
                        fmaxf(mred[tid * 4 + 2], mred[tid * 4 + 3]));
        int row = b * NTOK + m0 + tid;
        g_max[row] = v * g_inva[row];
    }
}

// ---------------- final: MLP logit + softmax + aggregation -------------------
__global__ void k_final(const float* __restrict__ seq_a,
                        const void* __restrict__ mask_a,
                        const float* __restrict__ w1, const float* __restrict__ b1,
                        const float* __restrict__ w2, const float* __restrict__ b2,
                        float* __restrict__ out) {
    int br = blockIdx.x;
    int t  = threadIdx.x;
    __shared__ float wrd[64], mn[64], mx[64], feat[128], attn[64], red[256];

    if (t < 64) {
        int tok = br * RVL + t;
        wrd[t] = g_word[tok];
        mn[t]  = g_mean[tok];
        mx[t]  = g_max[tok];
    }
    __syncthreads();
    if (t < 128) {
        int l = t >> 1;
        feat[t] = ((t & 1) ? mx[l] : mn[l]) * wrd[l];
    }
    __syncthreads();

    float acc = b1[t];
#pragma unroll 4
    for (int f = 0; f < 128; f++) acc += feat[f] * w1[f * HID + t];
    red[t] = tanhf(acc) * w2[t];
    __syncthreads();
    for (int s = 128; s > 0; s >>= 1) {
        if (t < s) red[t] += red[t + s];
        __syncthreads();
    }
    if (t == 0) out[br] = red[0] + b2[0];

    if (t == 0) {
        float m = -CUDART_INF_F;
        for (int l = 0; l < 64; l++) {
            float s = mask_at(mask_a, br * RVL + l) ? wrd[l] : NEGV;
            attn[l] = s;
            if (s > m) m = s;
        }
        float ssum = 0.f;
        for (int l = 0; l < 64; l++) {
            float e = expf(attn[l] - m);
            attn[l] = e;
            ssum += e;
        }
        float inv = 1.0f / ssum;
        for (int l = 0; l < 64; l++) attn[l] *= inv;
    }
    __syncthreads();

    const float* A = seq_a + (size_t)br * RVL * H;
    float agg = 0.f;
#pragma unroll 8
    for (int l = 0; l < 64; l++) agg += attn[l] * A[(size_t)l * H + t];
    out[BZ * RVN + br * H + t] = agg;
}

// ---------------- launch ------------------------------------------------------
extern "C" void kernel_launch(void* const* d_in, const int* in_sizes, int n_in,
                              void* d_out, int out_size) {
    const float* seq_a = (const float*)d_in[0];
    const float* seq_b = (const float*)d_in[1];
    const void*  mask_a = d_in[2];
    const void*  mask_b = d_in[3];
    const float* w_word = (const float*)d_in[4];
    const float* b_word = (const float*)d_in[5];
    const float* w1 = (const float*)d_in[6];
    const float* b1 = (const float*)d_in[7];
    const float* w2 = (const float*)d_in[8];
    const float* b2 = (const float*)d_in[9];
    float* out = (float*)d_out;

    cudaFuncSetAttribute(k_gemm_max, cudaFuncAttributeMaxDynamicSharedMemorySize,
                         SMEM_BYTES);

    k_detect_denom<<<1, 1024>>>((const unsigned char*)mask_b, mask_b);
    k_prep_b<<<BZ * NTOK / 8, 256>>>(seq_b);
    k_sb_part<<<dim3(32, BZ), 256>>>(seq_b, mask_b);
    k_sb_reduce<<<BZ, 256>>>();
    k_prep_a<<<BZ * NTOK / 8, 256>>>(seq_a, mask_a, w_word, b_word);
    k_gemm_max<<<dim3(16, BZ), 256, SMEM_BYTES>>>();
    k_final<<<BZ * RVN, 256>>>(seq_a, mask_a, w1, b1, w2, b2, out);
}

// round 8
// speedup vs baseline: 1.1288x; 1.1288x over previous
#include <cuda_runtime.h>
#include <cuda_bf16.h>
#include <math_constants.h>
#include <cstdint>

#define BZ   32
#define RVN  16
#define RVL  64
#define H    256
#define NTOK 1024
#define HID  256
#define EPSF 1e-8f
#define NEGV -100000000.0f

// ---------------- scratch ----------------------------------------------------
__device__ __align__(16) float g_invb[BZ * NTOK];
__device__ __align__(16) float g_sb_part[16][BZ][H];
__device__ __align__(16) float g_sb[BZ * H];
__device__ __align__(16) float g_denom[BZ];
__device__ __align__(16) float g_word[BZ * NTOK];
__device__ __align__(16) float g_inva[BZ * NTOK];
__device__ __align__(16) float g_mean[BZ * NTOK];
__device__ __align__(16) float g_max[BZ * NTOK];
__device__ int g_mask_byte;
// bf16 hi/lo split operands (A raw, B pre-scaled by 1/||b||), row-major [tok][256]
__device__ __align__(16) __nv_bfloat16 g_ah[BZ * NTOK * H];
__device__ __align__(16) __nv_bfloat16 g_al[BZ * NTOK * H];
__device__ __align__(16) __nv_bfloat16 g_bh[BZ * NTOK * H];
__device__ __align__(16) __nv_bfloat16 g_bl[BZ * NTOK * H];

__device__ __forceinline__ bool mask_at(const void* m, int i) {
    if (g_mask_byte) return ((const unsigned char*)m)[i] != 0;
    return ((const unsigned int*)m)[i] != 0u;
}
__device__ __forceinline__ float dot4(float4 a, float4 b) {
    return a.x * b.x + a.y * b.y + a.z * b.z + a.w * b.w;
}
__device__ __forceinline__ void cvt4(float4 v, float s,
                                     __nv_bfloat16* hp, __nv_bfloat16* lp) {
    float x0 = v.x * s, x1 = v.y * s, x2 = v.z * s, x3 = v.w * s;
    __nv_bfloat16 h0 = __float2bfloat16(x0), h1 = __float2bfloat16(x1);
    __nv_bfloat16 h2 = __float2bfloat16(x2), h3 = __float2bfloat16(x3);
    __nv_bfloat16 l0 = __float2bfloat16(x0 - __bfloat162float(h0));
    __nv_bfloat16 l1 = __float2bfloat16(x1 - __bfloat162float(h1));
    __nv_bfloat16 l2 = __float2bfloat16(x2 - __bfloat162float(h2));
    __nv_bfloat16 l3 = __float2bfloat16(x3 - __bfloat162float(h3));
    uint2 hu, lu;
    hu.x = (unsigned)__bfloat16_as_ushort(h0) | ((unsigned)__bfloat16_as_ushort(h1) << 16);
    hu.y = (unsigned)__bfloat16_as_ushort(h2) | ((unsigned)__bfloat16_as_ushort(h3) << 16);
    lu.x = (unsigned)__bfloat16_as_ushort(l0) | ((unsigned)__bfloat16_as_ushort(l1) << 16);
    lu.y = (unsigned)__bfloat16_as_ushort(l2) | ((unsigned)__bfloat16_as_ushort(l3) << 16);
    *(uint2*)hp = hu;
    *(uint2*)lp = lu;
}

__device__ __forceinline__ uint32_t smem_u32(const void* p) {
    uint32_t a;
    asm("{ .reg .u64 t; cvta.to.shared.u64 t, %1; cvt.u32.u64 %0, t; }"
        : "=r"(a) : "l"(p));
    return a;
}
__device__ __forceinline__ void cpa16(uint32_t dst, const void* src) {
    asm volatile("cp.async.cg.shared.global [%0], [%1], 16;" :: "r"(dst), "l"(src));
}
__device__ __forceinline__ void ldsm4(uint32_t addr, uint32_t* r) {
    asm volatile("ldmatrix.sync.aligned.m8n8.x4.shared.b16 {%0,%1,%2,%3}, [%4];"
                 : "=r"(r[0]), "=r"(r[1]), "=r"(r[2]), "=r"(r[3]) : "r"(addr));
}
__device__ __forceinline__ void mma16816(float* c, const uint32_t* a,
                                         uint32_t b0, uint32_t b1) {
    asm volatile(
        "mma.sync.aligned.m16n8k16.row.col.f32.bf16.bf16.f32 "
        "{%0,%1,%2,%3}, {%4,%5,%6,%7}, {%8,%9}, {%0,%1,%2,%3};"
        : "+f"(c[0]), "+f"(c[1]), "+f"(c[2]), "+f"(c[3])
        : "r"(a[0]), "r"(a[1]), "r"(a[2]), "r"(a[3]), "r"(b0), "r"(b1));
}

// ---------------- fused mask-width detect + per-batch denom ------------------
__global__ void k_detect_denom(const unsigned char* __restrict__ mbraw,
                               const void* __restrict__ mask_b) {
    __shared__ int mbyte;
    int t = threadIdx.x;  // 1024 threads
    if (t == 0) {
        int cnt = 0;
        for (int i = 0; i < 1024; i++) cnt += mbraw[i * 4 + 1] ? 1 : 0;
        int v = (cnt > 64) ? 1 : 0;
        g_mask_byte = v;
        mbyte = v;
    }
    __syncthreads();
    int b = t >> 5, lane = t & 31;
    int c = 0;
    for (int q = lane; q < NTOK; q += 32) {
        bool m = mbyte ? (((const unsigned char*)mask_b)[b * NTOK + q] != 0)
                       : (((const unsigned int*)mask_b)[b * NTOK + q] != 0u);
        c += m ? 1 : 0;
    }
#pragma unroll
    for (int off = 16; off > 0; off >>= 1)
        c += __shfl_xor_sync(0xffffffffu, c, off);
    if (lane == 0) g_denom[b] = fmaxf((float)c, 1.0f);
}

// ---------------- b prep: invb + bf16 hi/lo + masked partial sums ------------
// Block = 64 consecutive tokens of one batch (512 blocks). Warp = 8 tokens.
__global__ void k_prep_b(const float* __restrict__ seq_b,
                         const void* __restrict__ mask_b) {
    __shared__ float s[8][H];
    int tok0 = blockIdx.x * 64;
    int b = tok0 >> 10;
    int chunk = blockIdx.x & 15;
    int wid = threadIdx.x >> 5, lane = threadIdx.x & 31;

    float4 acc0 = {0.f, 0.f, 0.f, 0.f}, acc1 = {0.f, 0.f, 0.f, 0.f};
#pragma unroll
    for (int i = 0; i < 8; i++) {
        int tok = tok0 + wid * 8 + i;
        const float4* p = (const float4*)(seq_b + (size_t)tok * H);
        float4 v0 = p[lane], v1 = p[lane + 32];
        float ss = dot4(v0, v0) + dot4(v1, v1);
#pragma unroll
        for (int off = 16; off > 0; off >>= 1)
            ss += __shfl_xor_sync(0xffffffffu, ss, off);
        float ib = 1.0f / (sqrtf(ss) + EPSF);
        if (lane == 0) g_invb[tok] = ib;
        size_t base = (size_t)tok * H;
        cvt4(v0, ib, g_bh + base + lane * 4, g_bl + base + lane * 4);
        cvt4(v1, ib, g_bh + base + 128 + lane * 4, g_bl + base + 128 + lane * 4);
        if (mask_at(mask_b, tok)) {
            acc0.x += v0.x * ib; acc0.y += v0.y * ib;
            acc0.z += v0.z * ib; acc0.w += v0.w * ib;
            acc1.x += v1.x * ib; acc1.y += v1.y * ib;
            acc1.z += v1.z * ib; acc1.w += v1.w * ib;
        }
    }
    *(float4*)&s[wid][lane * 4] = acc0;
    *(float4*)&s[wid][128 + lane * 4] = acc1;
    __syncthreads();
    int t = threadIdx.x;
    float sum = 0.f;
#pragma unroll
    for (int w = 0; w < 8; w++) sum += s[w][t];
    g_sb_part[chunk][b][t] = sum;
}

__global__ void k_sb_reduce() {
    int b = blockIdx.x, t = threadIdx.x;
    float s = 0.f;
#pragma unroll
    for (int c = 0; c < 16; c++) s += g_sb_part[c][b][t];
    g_sb[b * H + t] = s;
}

// ---------------- a prep: word/inva/mean + bf16 hi/lo of a -------------------
__global__ void k_prep_a(const float* __restrict__ seq_a,
                         const void* __restrict__ mask_a,
                         const float* __restrict__ w_word,
                         const float* __restrict__ b_word) {
    int tok  = blockIdx.x * 8 + (threadIdx.x >> 5);
    int lane = threadIdx.x & 31;
    int b    = tok >> 10;
    const float4* pa = (const float4*)(seq_a + (size_t)tok * H);
    const float4* pw = (const float4*)w_word;
    const float4* ps = (const float4*)(g_sb + b * H);
    float4 a0 = pa[lane], a1 = pa[lane + 32];
    float4 w0 = pw[lane], w1v = pw[lane + 32];
    float4 s0 = ps[lane], s1 = ps[lane + 32];
    float ss = dot4(a0, a0) + dot4(a1, a1);
    float dw = dot4(a0, w0) + dot4(a1, w1v);
    float ds = dot4(a0, s0) + dot4(a1, s1);
#pragma unroll
    for (int off = 16; off > 0; off >>= 1) {
        ss += __shfl_xor_sync(0xffffffffu, ss, off);
        dw += __shfl_xor_sync(0xffffffffu, dw, off);
        ds += __shfl_xor_sync(0xffffffffu, ds, off);
    }
    float inva = 1.0f / (sqrtf(ss) + EPSF);
    if (lane == 0) {
        float ma   = mask_at(mask_a, tok) ? 1.0f : 0.0f;
        g_word[tok] = (dw + b_word[0]) * ma;
        g_inva[tok] = inva;
        g_mean[tok] = inva * ds / g_denom[b];
    }
    size_t base = (size_t)tok * H;
    cvt4(a0, 1.0f, g_ah + base + lane * 4, g_al + base + lane * 4);
    cvt4(a1, 1.0f, g_ah + base + 128 + lane * 4, g_al + base + 128 + lane * 4);
}

// ---------------- HMMA GEMM with row-max epilogue -----------------------------
// BM=128: A hi/lo full-K in smem (128KB, cp.async), B 8 n-tiles x 4 k-chunks
// double-buffered (2x32KB). 8 warps = 4 wm x 2 wn (32 rows x 64 cols each).
// 3-pass bf16 hi/lo. Total smem 192KB -> 1 block/SM.
#define OFF_AL 4096   // uint4 units
#define OFF_B0 8192
#define SMEM_BYTES (12288 * 16)

__global__ __launch_bounds__(256, 1) void k_gemm_max() {
    extern __shared__ __align__(128) unsigned char smraw[];
    const uint32_t smb = smem_u32(smraw);

    const int b   = blockIdx.y;
    const int m0  = blockIdx.x * 128;
    const int tid = threadIdx.x, wid = tid >> 5, lane = tid & 31;
    const int wm = wid & 3, wn = wid >> 2;
    const int g = lane >> 3, ril = lane & 7;

    const uint4* gah = (const uint4*)g_ah + (size_t)(b * NTOK + m0) * 32;
    const uint4* gal = (const uint4*)g_al + (size_t)(b * NTOK + m0) * 32;
    const uint4* gbh = (const uint4*)g_bh + (size_t)b * NTOK * 32;
    const uint4* gbl = (const uint4*)g_bl + (size_t)b * NTOK * 32;

    // A: 128 rows x 32 uint4 hi (at 0) + lo (at OFF_AL), swizzled; one group
#pragma unroll
    for (int i = 0; i < 16; i++) {
        int idx = tid + i * 256;
        int r = idx >> 5, c = idx & 31, cs = c ^ (r & 7);
        cpa16(smb + (uint32_t)(r * 32 + cs) * 16, gah + r * 32 + c);
        cpa16(smb + (uint32_t)(OFF_AL + r * 32 + cs) * 16, gal + r * 32 + c);
    }
    asm volatile("cp.async.commit_group;" ::: "memory");

    // B chunk loader: n-tile nt (128 rows), k-chunk kc (64 cols) into buf
    auto loadB = [&](int nt, int kc, int buf) {
        uint32_t base = smb + (uint32_t)(OFF_B0 + buf * 2048) * 16;
#pragma unroll
        for (int i = 0; i < 4; i++) {
            int idx = tid + i * 256;
            int n = idx >> 3, c = idx & 7, cs = c ^ (n & 7);
            size_t gi = (size_t)(nt * 128 + n) * 32 + kc * 8 + c;
            cpa16(base + (uint32_t)(n * 8 + cs) * 16, gbh + gi);
            cpa16(base + (uint32_t)(1024 + n * 8 + cs) * 16, gbl + gi);
        }
        asm volatile("cp.async.commit_group;" ::: "memory");
    };
    loadB(0, 0, 0);

    float pm[2][2];
    pm[0][0] = pm[0][1] = pm[1][0] = pm[1][1] = -CUDART_INF_F;
    float acc[2][8][4];

    for (int it = 0; it < 32; it++) {
        int kc = it & 3, buf = it & 1;
        if (it > 0) __syncthreads();  // everyone done reading buf^1
        if (it < 31) {
            int nit = it + 1;
            loadB(nit >> 2, nit & 3, buf ^ 1);
            asm volatile("cp.async.wait_group 1;" ::: "memory");
        } else {
            asm volatile("cp.async.wait_group 0;" ::: "memory");
        }
        __syncthreads();

        if (kc == 0) {
#pragma unroll
            for (int mt = 0; mt < 2; mt++)
#pragma unroll
                for (int n = 0; n < 8; n++)
#pragma unroll
                    for (int q = 0; q < 4; q++) acc[mt][n][q] = 0.f;
        }

#pragma unroll
        for (int ks = 0; ks < 4; ks++) {
            uint32_t ah[2][4], al[2][4], bh[4][4], bl[4][4];
#pragma unroll
            for (int mt = 0; mt < 2; mt++) {
                int r = wm * 32 + mt * 16 + ((g & 1) << 3) + ril;
                int c = kc * 8 + ks * 2 + (g >> 1);
                int cs = c ^ (r & 7);
                ldsm4(smb + (uint32_t)(r * 32 + cs) * 16, ah[mt]);
                ldsm4(smb + (uint32_t)(OFF_AL + r * 32 + cs) * 16, al[mt]);
            }
#pragma unroll
            for (int np = 0; np < 4; np++) {
                int r = wn * 64 + np * 16 + ((g & 1) << 3) + ril;
                int c = ks * 2 + (g >> 1);
                int cs = c ^ (r & 7);
                uint32_t base = (uint32_t)(OFF_B0 + buf * 2048 + r * 8 + cs);
                ldsm4(smb + base * 16, bh[np]);
                ldsm4(smb + (base + 1024) * 16, bl[np]);
            }
            // B x4 frags: [0]={n0-7,kLo} [1]={n8-15,kLo} [2]={n0-7,kHi} [3]={n8-15,kHi}
#pragma unroll
            for (int mt = 0; mt < 2; mt++)
#pragma unroll
                for (int np = 0; np < 4; np++)
#pragma unroll
                    for (int sub = 0; sub < 2; sub++) {
                        float* c4 = acc[mt][np * 2 + sub];
                        uint32_t bx0 = bh[np][sub], bx1 = bh[np][sub + 2];
                        uint32_t by0 = bl[np][sub], by1 = bl[np][sub + 2];
                        mma16816(c4, ah[mt], bx0, bx1);
                        mma16816(c4, ah[mt], by0, by1);
                        mma16816(c4, al[mt], bx0, bx1);
                    }
        }

        if (kc == 3) {
#pragma unroll
            for (int mt = 0; mt < 2; mt++)
#pragma unroll
                for (int n = 0; n < 8; n++) {
                    pm[mt][0] = fmaxf(pm[mt][0], fmaxf(acc[mt][n][0], acc[mt][n][1]));
                    pm[mt][1] = fmaxf(pm[mt][1], fmaxf(acc[mt][n][2], acc[mt][n][3]));
                }
        }
    }

    // cross-lane + cross-warp max: 128 rows x 2 wn
    __syncthreads();
    float* mred = (float*)smraw;
#pragma unroll
    for (int mt = 0; mt < 2; mt++)
#pragma unroll
        for (int hf = 0; hf < 2; hf++) {
            float v = pm[mt][hf];
            v = fmaxf(v, __shfl_xor_sync(0xffffffffu, v, 1));
            v = fmaxf(v, __shfl_xor_sync(0xffffffffu, v, 2));
            if ((lane & 3) == 0)
                mred[(wm * 32 + mt * 16 + hf * 8 + (lane >> 2)) * 2 + wn] = v;
        }
    __syncthreads();
    if (tid < 128) {
        float v = fmaxf(mred[tid * 2], mred[tid * 2 + 1]);
        int row = b * NTOK + m0 + tid;
        g_max[row] = v * g_inva[row];
    }
}

// ---------------- final: MLP logit + softmax + aggregation -------------------
__global__ void k_final(const float* __restrict__ seq_a,
                        const void* __restrict__ mask_a,
                        const float* __restrict__ w1, const float* __restrict__ b1,
                        const float* __restrict__ w2, const float* __restrict__ b2,
                        float* __restrict__ out) {
    int br = blockIdx.x;
    int t  = threadIdx.x;
    __shared__ float wrd[64], mn[64], mx[64], feat[128], attn[64], red[256];

    if (t < 64) {
        int tok = br * RVL + t;
        wrd[t] = g_word[tok];
        mn[t]  = g_mean[tok];
        mx[t]  = g_max[tok];
    }
    __syncthreads();
    if (t < 128) {
        int l = t >> 1;
        feat[t] = ((t & 1) ? mx[l] : mn[l]) * wrd[l];
    }
    __syncthreads();

    float acc = b1[t];
#pragma unroll 4
    for (int f = 0; f < 128; f++) acc += feat[f] * w1[f * HID + t];
    red[t] = tanhf(acc) * w2[t];
    __syncthreads();
    for (int s = 128; s > 0; s >>= 1) {
        if (t < s) red[t] += red[t + s];
        __syncthreads();
    }
    if (t == 0) out[br] = red[0] + b2[0];

    if (t == 0) {
        float m = -CUDART_INF_F;
        for (int l = 0; l < 64; l++) {
            float s = mask_at(mask_a, br * RVL + l) ? wrd[l] : NEGV;
            attn[l] = s;
            if (s > m) m = s;
        }
        float ssum = 0.f;
        for (int l = 0; l < 64; l++) {
            float e = expf(attn[l] - m);
            attn[l] = e;
            ssum += e;
        }
        float inv = 1.0f / ssum;
        for (int l = 0; l < 64; l++) attn[l] *= inv;
    }
    __syncthreads();

    const float* A = seq_a + (size_t)br * RVL * H;
    float agg = 0.f;
#pragma unroll 8
    for (int l = 0; l < 64; l++) agg += attn[l] * A[(size_t)l * H + t];
    out[BZ * RVN + br * H + t] = agg;
}

// ---------------- launch ------------------------------------------------------
extern "C" void kernel_launch(void* const* d_in, const int* in_sizes, int n_in,
                              void* d_out, int out_size) {
    const float* seq_a = (const float*)d_in[0];
    const float* seq_b = (const float*)d_in[1];
    const void*  mask_a = d_in[2];
    const void*  mask_b = d_in[3];
    const float* w_word = (const float*)d_in[4];
    const float* b_word = (const float*)d_in[5];
    const float* w1 = (const float*)d_in[6];
    const float* b1 = (const float*)d_in[7];
    const float* w2 = (const float*)d_in[8];
    const float* b2 = (const float*)d_in[9];
    float* out = (float*)d_out;

    cudaFuncSetAttribute(k_gemm_max, cudaFuncAttributeMaxDynamicSharedMemorySize,
                         SMEM_BYTES);

    k_detect_denom<<<1, 1024>>>((const unsigned char*)mask_b, mask_b);
    k_prep_b<<<BZ * NTOK / 64, 256>>>(seq_b, mask_b);
    k_sb_reduce<<<BZ, 256>>>();
    k_prep_a<<<BZ * NTOK / 8, 256>>>(seq_a, mask_a, w_word, b_word);
    k_gemm_max<<<dim3(8, BZ), 256, SMEM_BYTES>>>();
    k_final<<<BZ * RVN, 256>>>(seq_a, mask_a, w1, b1, w2, b2, out);
}

// round 10
// speedup vs baseline: 1.1495x; 1.0183x over previous
#include <cuda_runtime.h>
#include <cuda_bf16.h>
#include <math_constants.h>
#include <cstdint>

#define BZ   32
#define RVN  16
#define RVL  64
#define H    256
#define NTOK 1024
#define HID  256
#define EPSF 1e-8f
#define NEGV -100000000.0f

// ---------------- scratch ----------------------------------------------------
__device__ __align__(16) float g_invb[BZ * NTOK];
__device__ __align__(16) float g_sb_part[16][BZ][H];
__device__ __align__(16) float g_sb[BZ * H];
__device__ __align__(16) float g_denom[BZ];
__device__ __align__(16) float g_word[BZ * NTOK];
__device__ __align__(16) float g_inva[BZ * NTOK];
__device__ __align__(16) float g_max[BZ * NTOK];
__device__ int g_mask_byte;
// bf16 hi/lo split operands (A raw, B pre-scaled by 1/||b||), row-major [tok][256]
__device__ __align__(16) __nv_bfloat16 g_ah[BZ * NTOK * H];
__device__ __align__(16) __nv_bfloat16 g_al[BZ * NTOK * H];
__device__ __align__(16) __nv_bfloat16 g_bh[BZ * NTOK * H];
__device__ __align__(16) __nv_bfloat16 g_bl[BZ * NTOK * H];

__device__ __forceinline__ bool mask_at(const void* m, int i) {
    if (g_mask_byte) return ((const unsigned char*)m)[i] != 0;
    return ((const unsigned int*)m)[i] != 0u;
}
__device__ __forceinline__ float dot4(float4 a, float4 b) {
    return a.x * b.x + a.y * b.y + a.z * b.z + a.w * b.w;
}
__device__ __forceinline__ void cvt4(float4 v, float s,
                                     __nv_bfloat16* hp, __nv_bfloat16* lp) {
    float x0 = v.x * s, x1 = v.y * s, x2 = v.z * s, x3 = v.w * s;
    __nv_bfloat16 h0 = __float2bfloat16(x0), h1 = __float2bfloat16(x1);
    __nv_bfloat16 h2 = __float2bfloat16(x2), h3 = __float2bfloat16(x3);
    __nv_bfloat16 l0 = __float2bfloat16(x0 - __bfloat162float(h0));
    __nv_bfloat16 l1 = __float2bfloat16(x1 - __bfloat162float(h1));
    __nv_bfloat16 l2 = __float2bfloat16(x2 - __bfloat162float(h2));
    __nv_bfloat16 l3 = __float2bfloat16(x3 - __bfloat162float(h3));
    uint2 hu, lu;
    hu.x = (unsigned)__bfloat16_as_ushort(h0) | ((unsigned)__bfloat16_as_ushort(h1) << 16);
    hu.y = (unsigned)__bfloat16_as_ushort(h2) | ((unsigned)__bfloat16_as_ushort(h3) << 16);
    lu.x = (unsigned)__bfloat16_as_ushort(l0) | ((unsigned)__bfloat16_as_ushort(l1) << 16);
    lu.y = (unsigned)__bfloat16_as_ushort(l2) | ((unsigned)__bfloat16_as_ushort(l3) << 16);
    *(uint2*)hp = hu;
    *(uint2*)lp = lu;
}

__device__ __forceinline__ uint32_t smem_u32(const void* p) {
    uint32_t a;
    asm("{ .reg .u64 t; cvta.to.shared.u64 t, %1; cvt.u32.u64 %0, t; }"
        : "=r"(a) : "l"(p));
    return a;
}
__device__ __forceinline__ void cpa16(uint32_t dst, const void* src) {
    asm volatile("cp.async.cg.shared.global [%0], [%1], 16;" :: "r"(dst), "l"(src));
}
__device__ __forceinline__ void ldsm4(uint32_t addr, uint32_t* r) {
    asm volatile("ldmatrix.sync.aligned.m8n8.x4.shared.b16 {%0,%1,%2,%3}, [%4];"
                 : "=r"(r[0]), "=r"(r[1]), "=r"(r[2]), "=r"(r[3]) : "r"(addr));
}
__device__ __forceinline__ void mma16816(float* c, const uint32_t* a,
                                         uint32_t b0, uint32_t b1) {
    asm volatile(
        "mma.sync.aligned.m16n8k16.row.col.f32.bf16.bf16.f32 "
        "{%0,%1,%2,%3}, {%4,%5,%6,%7}, {%8,%9}, {%0,%1,%2,%3};"
        : "+f"(c[0]), "+f"(c[1]), "+f"(c[2]), "+f"(c[3])
        : "r"(a[0]), "r"(a[1]), "r"(a[2]), "r"(a[3]), "r"(b0), "r"(b1));
}

// ---------------- fused mask-width detect + per-batch denom ------------------
__global__ void k_detect_denom(const unsigned char* __restrict__ mbraw,
                               const void* __restrict__ mask_b) {
    __shared__ int mbyte;
    int t = threadIdx.x;  // 1024 threads
    if (t == 0) {
        int cnt = 0;
        for (int i = 0; i < 1024; i++) cnt += mbraw[i * 4 + 1] ? 1 : 0;
        int v = (cnt > 64) ? 1 : 0;
        g_mask_byte = v;
        mbyte = v;
    }
    __syncthreads();
    int b = t >> 5, lane = t & 31;
    int c = 0;
    for (int q = lane; q < NTOK; q += 32) {
        bool m = mbyte ? (((const unsigned char*)mask_b)[b * NTOK + q] != 0)
                       : (((const unsigned int*)mask_b)[b * NTOK + q] != 0u);
        c += m ? 1 : 0;
    }
#pragma unroll
    for (int off = 16; off > 0; off >>= 1)
        c += __shfl_xor_sync(0xffffffffu, c, off);
    if (lane == 0) g_denom[b] = fmaxf((float)c, 1.0f);
}

// ---------------- fused prep: A blocks (0..511) + B blocks (512..1023) -------
// Each block = 64 consecutive tokens; warp handles 8 tokens.
__global__ void k_prep_ab(const float* __restrict__ seq_a,
                          const float* __restrict__ seq_b,
                          const void* __restrict__ mask_a,
                          const void* __restrict__ mask_b,
                          const float* __restrict__ w_word,
                          const float* __restrict__ b_word) {
    __shared__ float s[8][H];
    int bx = blockIdx.x;
    int wid = threadIdx.x >> 5, lane = threadIdx.x & 31;

    if (bx < 512) {  // ---- A part: 512 blocks x 64 tokens = 32768 ----
        int tok0 = bx * 64;
        const float4* pw = (const float4*)w_word;
        float4 w0 = pw[lane], w1v = pw[lane + 32];
        float bw = b_word[0];
#pragma unroll
        for (int i = 0; i < 8; i++) {
            int tok = tok0 + wid * 8 + i;
            const float4* pa = (const float4*)(seq_a + (size_t)tok * H);
            float4 v0 = pa[lane], v1 = pa[lane + 32];
            float ss = dot4(v0, v0) + dot4(v1, v1);
            float dw = dot4(v0, w0) + dot4(v1, w1v);
#pragma unroll
            for (int off = 16; off > 0; off >>= 1) {
                ss += __shfl_xor_sync(0xffffffffu, ss, off);
                dw += __shfl_xor_sync(0xffffffffu, dw, off);
            }
            if (lane == 0) {
                float ma = mask_at(mask_a, tok) ? 1.0f : 0.0f;
                g_word[tok] = (dw + bw) * ma;
                g_inva[tok] = 1.0f / (sqrtf(ss) + EPSF);
            }
            size_t base = (size_t)tok * H;
            cvt4(v0, 1.0f, g_ah + base + lane * 4, g_al + base + lane * 4);
            cvt4(v1, 1.0f, g_ah + base + 128 + lane * 4, g_al + base + 128 + lane * 4);
        }
    } else {  // ---- B part: 512 blocks x 64 tokens ----
        int bi = bx - 512;
        int tok0 = bi * 64;
        int b = tok0 >> 10;
        int chunk = bi & 15;
        float4 acc0 = {0.f, 0.f, 0.f, 0.f}, acc1 = {0.f, 0.f, 0.f, 0.f};
#pragma unroll
        for (int i = 0; i < 8; i++) {
            int tok = tok0 + wid * 8 + i;
            const float4* p = (const float4*)(seq_b + (size_t)tok * H);
            float4 v0 = p[lane], v1 = p[lane + 32];
            float ss = dot4(v0, v0) + dot4(v1, v1);
#pragma unroll
            for (int off = 16; off > 0; off >>= 1)
                ss += __shfl_xor_sync(0xffffffffu, ss, off);
            float ib = 1.0f / (sqrtf(ss) + EPSF);
            if (lane == 0) g_invb[tok] = ib;
            size_t base = (size_t)tok * H;
            cvt4(v0, ib, g_bh + base + lane * 4, g_bl + base + lane * 4);
            cvt4(v1, ib, g_bh + base + 128 + lane * 4, g_bl + base + 128 + lane * 4);
            if (mask_at(mask_b, tok)) {
                acc0.x += v0.x * ib; acc0.y += v0.y * ib;
                acc0.z += v0.z * ib; acc0.w += v0.w * ib;
                acc1.x += v1.x * ib; acc1.y += v1.y * ib;
                acc1.z += v1.z * ib; acc1.w += v1.w * ib;
            }
        }
        *(float4*)&s[wid][lane * 4] = acc0;
        *(float4*)&s[wid][128 + lane * 4] = acc1;
        __syncthreads();
        int t = threadIdx.x;
        float sum = 0.f;
#pragma unroll
        for (int w = 0; w < 8; w++) sum += s[w][t];
        g_sb_part[chunk][b][t] = sum;
    }
}

__global__ void k_sb_reduce() {
    int b = blockIdx.x, t = threadIdx.x;
    float s = 0.f;
#pragma unroll
    for (int c = 0; c < 16; c++) s += g_sb_part[c][b][t];
    g_sb[b * H + t] = s;
}

// ---------------- HMMA GEMM with row-max epilogue -----------------------------
// BM=128: A hi/lo full-K in smem (128KB, cp.async). B: 3-stage cp.async pipeline
// (3 x 32KB). 8 warps = 4 wm x 2 wn (32 rows x 64 cols each). 3-pass bf16 hi/lo.
// Inner ks-loop software-pipelined with ping-pong fragment buffers.
#define OFF_AL 4096   // uint4 units
#define OFF_B0 8192
#define SMEM_BYTES (14336 * 16)   // 224KB

__global__ __launch_bounds__(256, 1) void k_gemm_max() {
    extern __shared__ __align__(128) unsigned char smraw[];
    const uint32_t smb = smem_u32(smraw);

    const int b   = blockIdx.y;
    const int m0  = blockIdx.x * 128;
    const int tid = threadIdx.x, wid = tid >> 5, lane = tid & 31;
    const int wm = wid & 3, wn = wid >> 2;
    const int g = lane >> 3, ril = lane & 7;

    const uint4* gah = (const uint4*)g_ah + (size_t)(b * NTOK + m0) * 32;
    const uint4* gal = (const uint4*)g_al + (size_t)(b * NTOK + m0) * 32;
    const uint4* gbh = (const uint4*)g_bh + (size_t)b * NTOK * 32;
    const uint4* gbl = (const uint4*)g_bl + (size_t)b * NTOK * 32;

    // A: 128 rows x 32 uint4 hi (at 0) + lo (at OFF_AL), swizzled; one group
#pragma unroll
    for (int i = 0; i < 16; i++) {
        int idx = tid + i * 256;
        int r = idx >> 5, c = idx & 31, cs = c ^ (r & 7);
        cpa16(smb + (uint32_t)(r * 32 + cs) * 16, gah + r * 32 + c);
        cpa16(smb + (uint32_t)(OFF_AL + r * 32 + cs) * 16, gal + r * 32 + c);
    }
    asm volatile("cp.async.commit_group;" ::: "memory");

    // B chunk loader: iteration index ii -> n-tile ii>>2, k-chunk ii&3, buf ii%3
    auto loadB = [&](int ii) {
        int nt = ii >> 2, kc = ii & 3, buf = ii % 3;
        uint32_t base = smb + (uint32_t)(OFF_B0 + buf * 2048) * 16;
#pragma unroll
        for (int i = 0; i < 4; i++) {
            int idx = tid + i * 256;
            int n = idx >> 3, c = idx & 7, cs = c ^ (n & 7);
            size_t gi = (size_t)(nt * 128 + n) * 32 + kc * 8 + c;
            cpa16(base + (uint32_t)(n * 8 + cs) * 16, gbh + gi);
            cpa16(base + (uint32_t)(1024 + n * 8 + cs) * 16, gbl + gi);
        }
        asm volatile("cp.async.commit_group;" ::: "memory");
    };
    loadB(0);
    loadB(1);

    float pm[2][2];
    pm[0][0] = pm[0][1] = pm[1][0] = pm[1][1] = -CUDART_INF_F;
    float acc[2][8][4];

    // ping-pong fragment buffers
    uint32_t fah[2][2][4], fal[2][2][4], fbh[2][4][4], fbl[2][4][4];

    auto ldfrags = [&](int kc, int ks, int pp, int buf) {
#pragma unroll
        for (int mt = 0; mt < 2; mt++) {
            int r = wm * 32 + mt * 16 + ((g & 1) << 3) + ril;
            int c = kc * 8 + ks * 2 + (g >> 1);
            int cs = c ^ (r & 7);
            ldsm4(smb + (uint32_t)(r * 32 + cs) * 16, fah[pp][mt]);
            ldsm4(smb + (uint32_t)(OFF_AL + r * 32 + cs) * 16, fal[pp][mt]);
        }
#pragma unroll
        for (int np = 0; np < 4; np++) {
            int r = wn * 64 + np * 16 + ((g & 1) << 3) + ril;
            int c = ks * 2 + (g >> 1);
            int cs = c ^ (r & 7);
            uint32_t base = (uint32_t)(OFF_B0 + buf * 2048 + r * 8 + cs);
            ldsm4(smb + base * 16, fbh[pp][np]);
            ldsm4(smb + (base + 1024) * 16, fbl[pp][np]);
        }
    };

    for (int it = 0; it < 32; it++) {
        int kc = it & 3, buf = it % 3;
        if (it < 31) {
            asm volatile("cp.async.wait_group 1;" ::: "memory");
        } else {
            asm volatile("cp.async.wait_group 0;" ::: "memory");
        }
        __syncthreads();
        if (it <= 29) loadB(it + 2);

        if (kc == 0) {
#pragma unroll
            for (int mt = 0; mt < 2; mt++)
#pragma unroll
                for (int n = 0; n < 8; n++)
#pragma unroll
                    for (int q = 0; q < 4; q++) acc[mt][n][q] = 0.f;
        }

        ldfrags(kc, 0, 0, buf);
#pragma unroll
        for (int ks = 0; ks < 4; ks++) {
            int cur = ks & 1;
            if (ks < 3) ldfrags(kc, ks + 1, cur ^ 1, buf);
            // B x4 frags: [0]={n0-7,kLo} [1]={n8-15,kLo} [2]={n0-7,kHi} [3]={n8-15,kHi}
#pragma unroll
            for (int mt = 0; mt < 2; mt++)
#pragma unroll
                for (int np = 0; np < 4; np++)
#pragma unroll
                    for (int sub = 0; sub < 2; sub++) {
                        float* c4 = acc[mt][np * 2 + sub];
                        uint32_t bx0 = fbh[cur][np][sub], bx1 = fbh[cur][np][sub + 2];
                        uint32_t by0 = fbl[cur][np][sub], by1 = fbl[cur][np][sub + 2];
                        mma16816(c4, fah[cur][mt], bx0, bx1);
                        mma16816(c4, fah[cur][mt], by0, by1);
                        mma16816(c4, fal[cur][mt], bx0, bx1);
                    }
        }

        if (kc == 3) {
#pragma unroll
            for (int mt = 0; mt < 2; mt++)
#pragma unroll
                for (int n = 0; n < 8; n++) {
                    pm[mt][0] = fmaxf(pm[mt][0], fmaxf(acc[mt][n][0], acc[mt][n][1]));
                    pm[mt][1] = fmaxf(pm[mt][1], fmaxf(acc[mt][n][2], acc[mt][n][3]));
                }
        }
    }

    // cross-lane + cross-warp max: 128 rows x 2 wn
    __syncthreads();
    float* mred = (float*)smraw;
#pragma unroll
    for (int mt = 0; mt < 2; mt++)
#pragma unroll
        for (int hf = 0; hf < 2; hf++) {
            float v = pm[mt][hf];
            v = fmaxf(v, __shfl_xor_sync(0xffffffffu, v, 1));
            v = fmaxf(v, __shfl_xor_sync(0xffffffffu, v, 2));
            if ((lane & 3) == 0)
                mred[(wm * 32 + mt * 16 + hf * 8 + (lane >> 2)) * 2 + wn] = v;
        }
    __syncthreads();
    if (tid < 128) {
        float v = fmaxf(mred[tid * 2], mred[tid * 2 + 1]);
        int row = b * NTOK + m0 + tid;
        g_max[row] = v * g_inva[row];
    }
}

// ---------------- final: mean + MLP logit + softmax + aggregation ------------
__global__ void k_final(const float* __restrict__ seq_a,
                        const void* __restrict__ mask_a,
                        const float* __restrict__ w1, const float* __restrict__ b1,
                        const float* __restrict__ w2, const float* __restrict__ b2,
                        float* __restrict__ out) {
    int br = blockIdx.x;
    int t  = threadIdx.x;
    int b  = br >> 4;
    int wid = t >> 5, lane = t & 31;
    __shared__ float wrd[64], mn[64], mx[64], feat[128], attn[64], red[256], sbs[H];

    if (t < 64) {
        int tok = br * RVL + t;
        wrd[t] = g_word[tok];
        mx[t]  = g_max[tok];
    }
    sbs[t] = g_sb[b * H + t];
    __syncthreads();

    // masked mean: mn[l] = inva_l * (a_l . sb) / denom
    {
        float dnm = g_denom[b];
        float4 sb0 = *(float4*)&sbs[lane * 4];
        float4 sb1 = *(float4*)&sbs[128 + lane * 4];
#pragma unroll
        for (int i = 0; i < 8; i++) {
            int l = wid * 8 + i;
            int tok = br * RVL + l;
            const float4* pa = (const float4*)(seq_a + (size_t)tok * H);
            float4 v0 = pa[lane], v1 = pa[lane + 32];
            float ds = dot4(v0, sb0) + dot4(v1, sb1);
#pragma unroll
            for (int off = 16; off > 0; off >>= 1)
                ds += __shfl_xor_sync(0xffffffffu, ds, off);
            if (lane == 0) mn[l] = g_inva[tok] * ds / dnm;
        }
    }
    __syncthreads();

    if (t < 128) {
        int l = t >> 1;
        feat[t] = ((t & 1) ? mx[l] : mn[l]) * wrd[l];
    }
    __syncthreads();

    float acc = b1[t];
#pragma unroll 4
    for (int f = 0; f < 128; f++) acc += feat[f] * w1[f * HID + t];
    red[t] = tanhf(acc) * w2[t];
    __syncthreads();
    for (int s = 128; s > 0; s >>= 1) {
        if (t < s) red[t] += red[t + s];
        __syncthreads();
    }
    if (t == 0) out[br] = red[0] + b2[0];

    if (t == 0) {
        float m = -CUDART_INF_F;
        for (int l = 0; l < 64; l++) {
            float s = mask_at(mask_a, br * RVL + l) ? wrd[l] : NEGV;
            attn[l] = s;
            if (s > m) m = s;
        }
        float ssum = 0.f;
        for (int l = 0; l < 64; l++) {
            float e = expf(attn[l] - m);
            attn[l] = e;
            ssum += e;
        }
        float inv = 1.0f / ssum;
        for (int l = 0; l < 64; l++) attn[l] *= inv;
    }
    __syncthreads();

    const float* A = seq_a + (size_t)br * RVL * H;
    float agg = 0.f;
#pragma unroll 8
    for (int l = 0; l < 64; l++) agg += attn[l] * A[(size_t)l * H + t];
    out[BZ * RVN + br * H + t] = agg;
}

// ---------------- launch ------------------------------------------------------
extern "C" void kernel_launch(void* const* d_in, const int* in_sizes, int n_in,
                              void* d_out, int out_size) {
    const float* seq_a = (const float*)d_in[0];
    const float* seq_b = (const float*)d_in[1];
    const void*  mask_a = d_in[2];
    const void*  mask_b = d_in[3];
    const float* w_word = (const float*)d_in[4];
    const float* b_word = (const float*)d_in[5];
    const float* w1 = (const float*)d_in[6];
    const float* b1 = (const float*)d_in[7];
    const float* w2 = (const float*)d_in[8];
    const float* b2 = (const float*)d_in[9];
    float* out = (float*)d_out;

    cudaFuncSetAttribute(k_gemm_max, cudaFuncAttributeMaxDynamicSharedMemorySize,
                         SMEM_BYTES);

    k_detect_denom<<<1, 1024>>>((const unsigned char*)mask_b, mask_b);
    k_prep_ab<<<1024, 256>>>(seq_a, seq_b, mask_a, mask_b, w_word, b_word);
    k_sb_reduce<<<BZ, 256>>>();
    k_gemm_max<<<dim3(8, BZ), 256, SMEM_BYTES>>>();
    k_final<<<BZ * RVN, 256>>>(seq_a, mask_a, w1, b1, w2, b2, out);
}

// round 11
// speedup vs baseline: 1.2046x; 1.0480x over previous
#include <cuda_runtime.h>
#include <cuda_bf16.h>
#include <math_constants.h>
#include <cstdint>

#define BZ   32
#define RVN  16
#define RVL  64
#define H    256
#define NTOK 1024
#define HID  256
#define EPSF 1e-8f
#define NEGV -100000000.0f

// ---------------- scratch ----------------------------------------------------
__device__ __align__(16) float g_invb[BZ * NTOK];
__device__ __align__(16) float g_sb_part[16][BZ][H];
__device__ __align__(16) float g_sb[BZ * H];
__device__ __align__(16) float g_denom[BZ];
__device__ __align__(16) float g_word[BZ * NTOK];
__device__ __align__(16) float g_inva[BZ * NTOK];
__device__ __align__(16) float g_max[BZ * NTOK];
__device__ int g_mask_byte;
// bf16 hi/lo split operands (A raw, B pre-scaled by 1/||b||), row-major [tok][256]
__device__ __align__(16) __nv_bfloat16 g_ah[BZ * NTOK * H];
__device__ __align__(16) __nv_bfloat16 g_al[BZ * NTOK * H];
__device__ __align__(16) __nv_bfloat16 g_bh[BZ * NTOK * H];
__device__ __align__(16) __nv_bfloat16 g_bl[BZ * NTOK * H];

__device__ __forceinline__ bool mask_at(const void* m, int i) {
    if (g_mask_byte) return ((const unsigned char*)m)[i] != 0;
    return ((const unsigned int*)m)[i] != 0u;
}
__device__ __forceinline__ float dot4(float4 a, float4 b) {
    return a.x * b.x + a.y * b.y + a.z * b.z + a.w * b.w;
}
__device__ __forceinline__ void cvt4(float4 v, float s,
                                     __nv_bfloat16* hp, __nv_bfloat16* lp) {
    float x0 = v.x * s, x1 = v.y * s, x2 = v.z * s, x3 = v.w * s;
    __nv_bfloat16 h0 = __float2bfloat16(x0), h1 = __float2bfloat16(x1);
    __nv_bfloat16 h2 = __float2bfloat16(x2), h3 = __float2bfloat16(x3);
    __nv_bfloat16 l0 = __float2bfloat16(x0 - __bfloat162float(h0));
    __nv_bfloat16 l1 = __float2bfloat16(x1 - __bfloat162float(h1));
    __nv_bfloat16 l2 = __float2bfloat16(x2 - __bfloat162float(h2));
    __nv_bfloat16 l3 = __float2bfloat16(x3 - __bfloat162float(h3));
    uint2 hu, lu;
    hu.x = (unsigned)__bfloat16_as_ushort(h0) | ((unsigned)__bfloat16_as_ushort(h1) << 16);
    hu.y = (unsigned)__bfloat16_as_ushort(h2) | ((unsigned)__bfloat16_as_ushort(h3) << 16);
    lu.x = (unsigned)__bfloat16_as_ushort(l0) | ((unsigned)__bfloat16_as_ushort(l1) << 16);
    lu.y = (unsigned)__bfloat16_as_ushort(l2) | ((unsigned)__bfloat16_as_ushort(l3) << 16);
    *(uint2*)hp = hu;
    *(uint2*)lp = lu;
}

__device__ __forceinline__ uint32_t smem_u32(const void* p) {
    uint32_t a;
    asm("{ .reg .u64 t; cvta.to.shared.u64 t, %1; cvt.u32.u64 %0, t; }"
        : "=r"(a) : "l"(p));
    return a;
}
__device__ __forceinline__ void cpa16(uint32_t dst, const void* src) {
    asm volatile("cp.async.cg.shared.global [%0], [%1], 16;" :: "r"(dst), "l"(src));
}
__device__ __forceinline__ void ldsm4(uint32_t addr, uint32_t* r) {
    asm volatile("ldmatrix.sync.aligned.m8n8.x4.shared.b16 {%0,%1,%2,%3}, [%4];"
                 : "=r"(r[0]), "=r"(r[1]), "=r"(r[2]), "=r"(r[3]) : "r"(addr));
}
__device__ __forceinline__ void mma16816(float* c, const uint32_t* a,
                                         uint32_t b0, uint32_t b1) {
    asm volatile(
        "mma.sync.aligned.m16n8k16.row.col.f32.bf16.bf16.f32 "
        "{%0,%1,%2,%3}, {%4,%5,%6,%7}, {%8,%9}, {%0,%1,%2,%3};"
        : "+f"(c[0]), "+f"(c[1]), "+f"(c[2]), "+f"(c[3])
        : "r"(a[0]), "r"(a[1]), "r"(a[2]), "r"(a[3]), "r"(b0), "r"(b1));
}

// ---------------- fused mask-width detect + per-batch denom ------------------
__global__ void k_detect_denom(const unsigned char* __restrict__ mbraw,
                               const void* __restrict__ mask_b) {
    __shared__ int mbyte;
    int t = threadIdx.x;  // 1024 threads
    if (t < 32) {  // warp 0: parallel byte-probe (32 lanes x 32 samples)
        int cnt = 0;
#pragma unroll
        for (int j = 0; j < 32; j++)
            cnt += mbraw[(t * 32 + j) * 4 + 1] ? 1 : 0;
#pragma unroll
        for (int off = 16; off > 0; off >>= 1)
            cnt += __shfl_xor_sync(0xffffffffu, cnt, off);
        if (t == 0) {
            int v = (cnt > 64) ? 1 : 0;
            g_mask_byte = v;
            mbyte = v;
        }
    }
    __syncthreads();
    int b = t >> 5, lane = t & 31;
    int c = 0;
    for (int q = lane; q < NTOK; q += 32) {
        bool m = mbyte ? (((const unsigned char*)mask_b)[b * NTOK + q] != 0)
                       : (((const unsigned int*)mask_b)[b * NTOK + q] != 0u);
        c += m ? 1 : 0;
    }
#pragma unroll
    for (int off = 16; off > 0; off >>= 1)
        c += __shfl_xor_sync(0xffffffffu, c, off);
    if (lane == 0) g_denom[b] = fmaxf((float)c, 1.0f);
}

// ---------------- fused prep: A blocks (0..511) + B blocks (512..1023) -------
// Each block = 64 consecutive tokens; warp handles 8 tokens.
__global__ void k_prep_ab(const float* __restrict__ seq_a,
                          const float* __restrict__ seq_b,
                          const void* __restrict__ mask_a,
                          const void* __restrict__ mask_b,
                          const float* __restrict__ w_word,
                          const float* __restrict__ b_word) {
    __shared__ float s[8][H];
    int bx = blockIdx.x;
    int wid = threadIdx.x >> 5, lane = threadIdx.x & 31;

    if (bx < 512) {  // ---- A part: 512 blocks x 64 tokens = 32768 ----
        int tok0 = bx * 64;
        const float4* pw = (const float4*)w_word;
        float4 w0 = pw[lane], w1v = pw[lane + 32];
        float bw = b_word[0];
#pragma unroll
        for (int i = 0; i < 8; i++) {
            int tok = tok0 + wid * 8 + i;
            const float4* pa = (const float4*)(seq_a + (size_t)tok * H);
            float4 v0 = pa[lane], v1 = pa[lane + 32];
            float ss = dot4(v0, v0) + dot4(v1, v1);
            float dw = dot4(v0, w0) + dot4(v1, w1v);
#pragma unroll
            for (int off = 16; off > 0; off >>= 1) {
                ss += __shfl_xor_sync(0xffffffffu, ss, off);
                dw += __shfl_xor_sync(0xffffffffu, dw, off);
            }
            if (lane == 0) {
                float ma = mask_at(mask_a, tok) ? 1.0f : 0.0f;
                g_word[tok] = (dw + bw) * ma;
                g_inva[tok] = 1.0f / (sqrtf(ss) + EPSF);
            }
            size_t base = (size_t)tok * H;
            cvt4(v0, 1.0f, g_ah + base + lane * 4, g_al + base + lane * 4);
            cvt4(v1, 1.0f, g_ah + base + 128 + lane * 4, g_al + base + 128 + lane * 4);
        }
    } else {  // ---- B part: 512 blocks x 64 tokens ----
        int bi = bx - 512;
        int tok0 = bi * 64;
        int b = tok0 >> 10;
        int chunk = bi & 15;
        float4 acc0 = {0.f, 0.f, 0.f, 0.f}, acc1 = {0.f, 0.f, 0.f, 0.f};
#pragma unroll
        for (int i = 0; i < 8; i++) {
            int tok = tok0 + wid * 8 + i;
            const float4* p = (const float4*)(seq_b + (size_t)tok * H);
            float4 v0 = p[lane], v1 = p[lane + 32];
            float ss = dot4(v0, v0) + dot4(v1, v1);
#pragma unroll
            for (int off = 16; off > 0; off >>= 1)
                ss += __shfl_xor_sync(0xffffffffu, ss, off);
            float ib = 1.0f / (sqrtf(ss) + EPSF);
            if (lane == 0) g_invb[tok] = ib;
            size_t base = (size_t)tok * H;
            cvt4(v0, ib, g_bh + base + lane * 4, g_bl + base + lane * 4);
            cvt4(v1, ib, g_bh + base + 128 + lane * 4, g_bl + base + 128 + lane * 4);
            if (mask_at(mask_b, tok)) {
                acc0.x += v0.x * ib; acc0.y += v0.y * ib;
                acc0.z += v0.z * ib; acc0.w += v0.w * ib;
                acc1.x += v1.x * ib; acc1.y += v1.y * ib;
                acc1.z += v1.z * ib; acc1.w += v1.w * ib;
            }
        }
        *(float4*)&s[wid][lane * 4] = acc0;
        *(float4*)&s[wid][128 + lane * 4] = acc1;
        __syncthreads();
        int t = threadIdx.x;
        float sum = 0.f;
#pragma unroll
        for (int w = 0; w < 8; w++) sum += s[w][t];
        g_sb_part[chunk][b][t] = sum;
    }
}

__global__ void k_sb_reduce() {
    int b = blockIdx.x, t = threadIdx.x;
    float s = 0.f;
#pragma unroll
    for (int c = 0; c < 16; c++) s += g_sb_part[c][b][t];
    g_sb[b * H + t] = s;
}

// ---------------- HMMA GEMM with row-max epilogue -----------------------------
// BM=128: A hi/lo full-K in smem (128KB, cp.async). B: 3-stage cp.async pipeline
// (3 x 32KB). 16 warps = 4 wm x 4 wn (32 rows x 32 cols each). 3-pass bf16 hi/lo.
// Inner ks-loop software-pipelined with ping-pong fragment buffers.
#define OFF_AL 4096   // uint4 units
#define OFF_B0 8192
#define SMEM_BYTES (14336 * 16)   // 224KB

__global__ __launch_bounds__(512, 1) void k_gemm_max() {
    extern __shared__ __align__(128) unsigned char smraw[];
    const uint32_t smb = smem_u32(smraw);

    const int b   = blockIdx.y;
    const int m0  = blockIdx.x * 128;
    const int tid = threadIdx.x, wid = tid >> 5, lane = tid & 31;
    const int wm = wid & 3, wn = wid >> 2;
    const int g = lane >> 3, ril = lane & 7;

    const uint4* gah = (const uint4*)g_ah + (size_t)(b * NTOK + m0) * 32;
    const uint4* gal = (const uint4*)g_al + (size_t)(b * NTOK + m0) * 32;
    const uint4* gbh = (const uint4*)g_bh + (size_t)b * NTOK * 32;
    const uint4* gbl = (const uint4*)g_bl + (size_t)b * NTOK * 32;

    // A: 128 rows x 32 uint4 hi (at 0) + lo (at OFF_AL), swizzled; one group
#pragma unroll
    for (int i = 0; i < 8; i++) {
        int idx = tid + i * 512;
        int r = idx >> 5, c = idx & 31, cs = c ^ (r & 7);
        cpa16(smb + (uint32_t)(r * 32 + cs) * 16, gah + r * 32 + c);
        cpa16(smb + (uint32_t)(OFF_AL + r * 32 + cs) * 16, gal + r * 32 + c);
    }
    asm volatile("cp.async.commit_group;" ::: "memory");

    // B chunk loader: iteration index ii -> n-tile ii>>2, k-chunk ii&3, buf ii%3
    auto loadB = [&](int ii) {
        int nt = ii >> 2, kc = ii & 3, buf = ii % 3;
        uint32_t base = smb + (uint32_t)(OFF_B0 + buf * 2048) * 16;
#pragma unroll
        for (int i = 0; i < 2; i++) {
            int idx = tid + i * 512;
            int n = idx >> 3, c = idx & 7, cs = c ^ (n & 7);
            size_t gi = (size_t)(nt * 128 + n) * 32 + kc * 8 + c;
            cpa16(base + (uint32_t)(n * 8 + cs) * 16, gbh + gi);
            cpa16(base + (uint32_t)(1024 + n * 8 + cs) * 16, gbl + gi);
        }
        asm volatile("cp.async.commit_group;" ::: "memory");
    };
    loadB(0);
    loadB(1);

    float pm[2][2];
    pm[0][0] = pm[0][1] = pm[1][0] = pm[1][1] = -CUDART_INF_F;
    float acc[2][4][4];

    // ping-pong fragment buffers
    uint32_t fah[2][2][4], fal[2][2][4], fbh[2][2][4], fbl[2][2][4];

    auto ldfrags = [&](int kc, int ks, int pp, int buf) {
#pragma unroll
        for (int mt = 0; mt < 2; mt++) {
            int r = wm * 32 + mt * 16 + ((g & 1) << 3) + ril;
            int c = kc * 8 + ks * 2 + (g >> 1);
            int cs = c ^ (r & 7);
            ldsm4(smb + (uint32_t)(r * 32 + cs) * 16, fah[pp][mt]);
            ldsm4(smb + (uint32_t)(OFF_AL + r * 32 + cs) * 16, fal[pp][mt]);
        }
#pragma unroll
        for (int np = 0; np < 2; np++) {
            int r = wn * 32 + np * 16 + ((g & 1) << 3) + ril;
            int c = ks * 2 + (g >> 1);
            int cs = c ^ (r & 7);
            uint32_t base = (uint32_t)(OFF_B0 + buf * 2048 + r * 8 + cs);
            ldsm4(smb + base * 16, fbh[pp][np]);
            ldsm4(smb + (base + 1024) * 16, fbl[pp][np]);
        }
    };

    for (int it = 0; it < 32; it++) {
        int kc = it & 3, buf = it % 3;
        if (it < 31) {
            asm volatile("cp.async.wait_group 1;" ::: "memory");
        } else {
            asm volatile("cp.async.wait_group 0;" ::: "memory");
        }
        __syncthreads();
        if (it <= 29) loadB(it + 2);

        if (kc == 0) {
#pragma unroll
            for (int mt = 0; mt < 2; mt++)
#pragma unroll
                for (int n = 0; n < 4; n++)
#pragma unroll
                    for (int q = 0; q < 4; q++) acc[mt][n][q] = 0.f;
        }

        ldfrags(kc, 0, 0, buf);
#pragma unroll
        for (int ks = 0; ks < 4; ks++) {
            int cur = ks & 1;
            if (ks < 3) ldfrags(kc, ks + 1, cur ^ 1, buf);
            // B x4 frags: [0]={n0-7,kLo} [1]={n8-15,kLo} [2]={n0-7,kHi} [3]={n8-15,kHi}
#pragma unroll
            for (int mt = 0; mt < 2; mt++)
#pragma unroll
                for (int np = 0; np < 2; np++)
#pragma unroll
                    for (int sub = 0; sub < 2; sub++) {
                        float* c4 = acc[mt][np * 2 + sub];
                        uint32_t bx0 = fbh[cur][np][sub], bx1 = fbh[cur][np][sub + 2];
                        uint32_t by0 = fbl[cur][np][sub], by1 = fbl[cur][np][sub + 2];
                        mma16816(c4, fah[cur][mt], bx0, bx1);
                        mma16816(c4, fah[cur][mt], by0, by1);
                        mma16816(c4, fal[cur][mt], bx0, bx1);
                    }
        }

        if (kc == 3) {
#pragma unroll
            for (int mt = 0; mt < 2; mt++)
#pragma unroll
                for (int n = 0; n < 4; n++) {
                    pm[mt][0] = fmaxf(pm[mt][0], fmaxf(acc[mt][n][0], acc[mt][n][1]));
                    pm[mt][1] = fmaxf(pm[mt][1], fmaxf(acc[mt][n][2], acc[mt][n][3]));
                }
        }
    }

    // cross-lane + cross-warp max: 128 rows x 4 wn
    __syncthreads();
    float* mred = (float*)smraw;
#pragma unroll
    for (int mt = 0; mt < 2; mt++)
#pragma unroll
        for (int hf = 0; hf < 2; hf++) {
            float v = pm[mt][hf];
            v = fmaxf(v, __shfl_xor_sync(0xffffffffu, v, 1));
            v = fmaxf(v, __shfl_xor_sync(0xffffffffu, v, 2));
            if ((lane & 3) == 0)
                mred[(wm * 32 + mt * 16 + hf * 8 + (lane >> 2)) * 4 + wn] = v;
        }
    __syncthreads();
    if (tid < 128) {
        float v = fmaxf(fmaxf(mred[tid * 4], mred[tid * 4 + 1]),
                        fmaxf(mred[tid * 4 + 2], mred[tid * 4 + 3]));
        int row = b * NTOK + m0 + tid;
        g_max[row] = v * g_inva[row];
    }
}

// ---------------- final: mean + MLP logit + softmax + aggregation ------------
__global__ void k_final(const float* __restrict__ seq_a,
                        const void* __restrict__ mask_a,
                        const float* __restrict__ w1, const float* __restrict__ b1,
                        const float* __restrict__ w2, const float* __restrict__ b2,
                        float* __restrict__ out) {
    int br = blockIdx.x;
    int t  = threadIdx.x;
    int b  = br >> 4;
    int wid = t >> 5, lane = t & 31;
    __shared__ float wrd[64], mn[64], mx[64], feat[128], attn[64], red[256], sbs[H];

    if (t < 64) {
        int tok = br * RVL + t;
        wrd[t] = g_word[tok];
        mx[t]  = g_max[tok];
    }
    sbs[t] = g_sb[b * H + t];
    __syncthreads();

    // masked mean: mn[l] = inva_l * (a_l . sb) / denom
    {
        float dnm = g_denom[b];
        float4 sb0 = *(float4*)&sbs[lane * 4];
        float4 sb1 = *(float4*)&sbs[128 + lane * 4];
#pragma unroll
        for (int i = 0; i < 8; i++) {
            int l = wid * 8 + i;
            int tok = br * RVL + l;
            const float4* pa = (const float4*)(seq_a + (size_t)tok * H);
            float4 v0 = pa[lane], v1 = pa[lane + 32];
            float ds = dot4(v0, sb0) + dot4(v1, sb1);
#pragma unroll
            for (int off = 16; off > 0; off >>= 1)
                ds += __shfl_xor_sync(0xffffffffu, ds, off);
            if (lane == 0) mn[l] = g_inva[tok] * ds / dnm;
        }
    }
    __syncthreads();

    if (t < 128) {
        int l = t >> 1;
        feat[t] = ((t & 1) ? mx[l] : mn[l]) * wrd[l];
    }
    __syncthreads();

    float acc = b1[t];
#pragma unroll 4
    for (int f = 0; f < 128; f++) acc += feat[f] * w1[f * HID + t];
    red[t] = tanhf(acc) * w2[t];
    __syncthreads();
    for (int s = 128; s > 0; s >>= 1) {
        if (t < s) red[t] += red[t + s];
        __syncthreads();
    }
    if (t == 0) out[br] = red[0] + b2[0];

    if (t == 0) {
        float m = -CUDART_INF_F;
        for (int l = 0; l < 64; l++) {
            float s = mask_at(mask_a, br * RVL + l) ? wrd[l] : NEGV;
            attn[l] = s;
            if (s > m) m = s;
        }
        float ssum = 0.f;
        for (int l = 0; l < 64; l++) {
            float e = expf(attn[l] - m);
            attn[l] = e;
            ssum += e;
        }
        float inv = 1.0f / ssum;
        for (int l = 0; l < 64; l++) attn[l] *= inv;
    }
    __syncthreads();

    const float* A = seq_a + (size_t)br * RVL * H;
    float agg = 0.f;
#pragma unroll 8
    for (int l = 0; l < 64; l++) agg += attn[l] * A[(size_t)l * H + t];
    out[BZ * RVN + br * H + t] = agg;
}

// ---------------- launch ------------------------------------------------------
extern "C" void kernel_launch(void* const* d_in, const int* in_sizes, int n_in,
                              void* d_out, int out_size) {
    const float* seq_a = (const float*)d_in[0];
    const float* seq_b = (const float*)d_in[1];
    const void*  mask_a = d_in[2];
    const void*  mask_b = d_in[3];
    const float* w_word = (const float*)d_in[4];
    const float* b_word = (const float*)d_in[5];
    const float* w1 = (const float*)d_in[6];
    const float* b1 = (const float*)d_in[7];
    const float* w2 = (const float*)d_in[8];
    const float* b2 = (const float*)d_in[9];
    float* out = (float*)d_out;

    cudaFuncSetAttribute(k_gemm_max, cudaFuncAttributeMaxDynamicSharedMemorySize,
                         SMEM_BYTES);

    k_detect_denom<<<1, 1024>>>((const unsigned char*)mask_b, mask_b);
    k_prep_ab<<<1024, 256>>>(seq_a, seq_b, mask_a, mask_b, w_word, b_word);
    k_sb_reduce<<<BZ, 256>>>();
    k_gemm_max<<<dim3(8, BZ), 512, SMEM_BYTES>>>();
    k_final<<<BZ * RVN, 256>>>(seq_a, mask_a, w1, b1, w2, b2, out);
}

// round 12
// speedup vs baseline: 1.5445x; 1.2821x over previous
#include <cuda_runtime.h>
#include <cuda_fp16.h>
#include <math_constants.h>
#include <cstdint>

#define BZ   32
#define RVN  16
#define RVL  64
#define H    256
#define NTOK 1024
#define HID  256
#define EPSF 1e-8f
#define NEGV -100000000.0f
#define RSCALE 1024.0f

// ---------------- scratch ----------------------------------------------------
__device__ __align__(16) float g_invb[BZ * NTOK];
__device__ __align__(16) float g_sb_part[16][BZ][H];
__device__ __align__(16) float g_sb[BZ * H];
__device__ __align__(16) float g_denom[BZ];
__device__ __align__(16) float g_word[BZ * NTOK];
__device__ __align__(16) float g_inva[BZ * NTOK];
__device__ __align__(16) float g_max[BZ * NTOK];
__device__ int g_mask_byte;
// fp16 operands: A plain fp16 (raw); B hi + scaled residual (pre-scaled by 1/||b||)
__device__ __align__(16) __half g_af[BZ * NTOK * H];
__device__ __align__(16) __half g_bh[BZ * NTOK * H];
__device__ __align__(16) __half g_bl[BZ * NTOK * H];

__device__ __forceinline__ bool mask_at(const void* m, int i) {
    if (g_mask_byte) return ((const unsigned char*)m)[i] != 0;
    return ((const unsigned int*)m)[i] != 0u;
}
__device__ __forceinline__ float dot4(float4 a, float4 b) {
    return a.x * b.x + a.y * b.y + a.z * b.z + a.w * b.w;
}
// A: 4 floats -> 4 fp16
__device__ __forceinline__ void cvt4_a(float4 v, __half* p) {
    __half2* d = (__half2*)p;
    d[0] = __floats2half2_rn(v.x, v.y);
    d[1] = __floats2half2_rn(v.z, v.w);
}
// B: scale by s, split into fp16 hi + scaled residual
__device__ __forceinline__ void cvt4_b(float4 v, float s, __half* hp, __half* lp) {
    float x0 = v.x * s, x1 = v.y * s, x2 = v.z * s, x3 = v.w * s;
    __half h0 = __float2half_rn(x0), h1 = __float2half_rn(x1);
    __half h2 = __float2half_rn(x2), h3 = __float2half_rn(x3);
    float r0 = (x0 - __half2float(h0)) * RSCALE;
    float r1 = (x1 - __half2float(h1)) * RSCALE;
    float r2 = (x2 - __half2float(h2)) * RSCALE;
    float r3 = (x3 - __half2float(h3)) * RSCALE;
    __half2* hd = (__half2*)hp;
    hd[0] = __halves2half2(h0, h1);
    hd[1] = __halves2half2(h2, h3);
    __half2* ld = (__half2*)lp;
    ld[0] = __floats2half2_rn(r0, r1);
    ld[1] = __floats2half2_rn(r2, r3);
}

__device__ __forceinline__ uint32_t smem_u32(const void* p) {
    uint32_t a;
    asm("{ .reg .u64 t; cvta.to.shared.u64 t, %1; cvt.u32.u64 %0, t; }"
        : "=r"(a) : "l"(p));
    return a;
}
__device__ __forceinline__ void cpa16(uint32_t dst, const void* src) {
    asm volatile("cp.async.cg.shared.global [%0], [%1], 16;" :: "r"(dst), "l"(src));
}
__device__ __forceinline__ void ldsm4(uint32_t addr, uint32_t* r) {
    asm volatile("ldmatrix.sync.aligned.m8n8.x4.shared.b16 {%0,%1,%2,%3}, [%4];"
                 : "=r"(r[0]), "=r"(r[1]), "=r"(r[2]), "=r"(r[3]) : "r"(addr));
}
__device__ __forceinline__ void mma16816h(float* c, const uint32_t* a,
                                          uint32_t b0, uint32_t b1) {
    asm volatile(
        "mma.sync.aligned.m16n8k16.row.col.f32.f16.f16.f32 "
        "{%0,%1,%2,%3}, {%4,%5,%6,%7}, {%8,%9}, {%0,%1,%2,%3};"
        : "+f"(c[0]), "+f"(c[1]), "+f"(c[2]), "+f"(c[3])
        : "r"(a[0]), "r"(a[1]), "r"(a[2]), "r"(a[3]), "r"(b0), "r"(b1));
}

// ---------------- fused mask-width detect + per-batch denom ------------------
__global__ void k_detect_denom(const unsigned char* __restrict__ mbraw,
                               const void* __restrict__ mask_b) {
    __shared__ int mbyte;
    int t = threadIdx.x;  // 1024 threads
    if (t < 32) {
        int cnt = 0;
#pragma unroll
        for (int j = 0; j < 32; j++)
            cnt += mbraw[(t * 32 + j) * 4 + 1] ? 1 : 0;
#pragma unroll
        for (int off = 16; off > 0; off >>= 1)
            cnt += __shfl_xor_sync(0xffffffffu, cnt, off);
        if (t == 0) {
            int v = (cnt > 64) ? 1 : 0;
            g_mask_byte = v;
            mbyte = v;
        }
    }
    __syncthreads();
    int b = t >> 5, lane = t & 31;
    int c = 0;
    for (int q = lane; q < NTOK; q += 32) {
        bool m = mbyte ? (((const unsigned char*)mask_b)[b * NTOK + q] != 0)
                       : (((const unsigned int*)mask_b)[b * NTOK + q] != 0u);
        c += m ? 1 : 0;
    }
#pragma unroll
    for (int off = 16; off > 0; off >>= 1)
        c += __shfl_xor_sync(0xffffffffu, c, off);
    if (lane == 0) g_denom[b] = fmaxf((float)c, 1.0f);
}

// ---------------- fused prep: A blocks (0..511) + B blocks (512..1023) -------
__global__ void k_prep_ab(const float* __restrict__ seq_a,
                          const float* __restrict__ seq_b,
                          const void* __restrict__ mask_a,
                          const void* __restrict__ mask_b,
                          const float* __restrict__ w_word,
                          const float* __restrict__ b_word) {
    __shared__ float s[8][H];
    int bx = blockIdx.x;
    int wid = threadIdx.x >> 5, lane = threadIdx.x & 31;

    if (bx < 512) {  // ---- A: fp16 convert + word + inva ----
        int tok0 = bx * 64;
        const float4* pw = (const float4*)w_word;
        float4 w0 = pw[lane], w1v = pw[lane + 32];
        float bw = b_word[0];
#pragma unroll
        for (int i = 0; i < 8; i++) {
            int tok = tok0 + wid * 8 + i;
            const float4* pa = (const float4*)(seq_a + (size_t)tok * H);
            float4 v0 = pa[lane], v1 = pa[lane + 32];
            float ss = dot4(v0, v0) + dot4(v1, v1);
            float dw = dot4(v0, w0) + dot4(v1, w1v);
#pragma unroll
            for (int off = 16; off > 0; off >>= 1) {
                ss += __shfl_xor_sync(0xffffffffu, ss, off);
                dw += __shfl_xor_sync(0xffffffffu, dw, off);
            }
            if (lane == 0) {
                float ma = mask_at(mask_a, tok) ? 1.0f : 0.0f;
                g_word[tok] = (dw + bw) * ma;
                g_inva[tok] = 1.0f / (sqrtf(ss) + EPSF);
            }
            size_t base = (size_t)tok * H;
            cvt4_a(v0, g_af + base + lane * 4);
            cvt4_a(v1, g_af + base + 128 + lane * 4);
        }
    } else {  // ---- B: normalize, split, masked partial sums ----
        int bi = bx - 512;
        int tok0 = bi * 64;
        int b = tok0 >> 10;
        int chunk = bi & 15;
        float4 acc0 = {0.f, 0.f, 0.f, 0.f}, acc1 = {0.f, 0.f, 0.f, 0.f};
#pragma unroll
        for (int i = 0; i < 8; i++) {
            int tok = tok0 + wid * 8 + i;
            const float4* p = (const float4*)(seq_b + (size_t)tok * H);
            float4 v0 = p[lane], v1 = p[lane + 32];
            float ss = dot4(v0, v0) + dot4(v1, v1);
#pragma unroll
            for (int off = 16; off > 0; off >>= 1)
                ss += __shfl_xor_sync(0xffffffffu, ss, off);
            float ib = 1.0f / (sqrtf(ss) + EPSF);
            if (lane == 0) g_invb[tok] = ib;
            size_t base = (size_t)tok * H;
            cvt4_b(v0, ib, g_bh + base + lane * 4, g_bl + base + lane * 4);
            cvt4_b(v1, ib, g_bh + base + 128 + lane * 4, g_bl + base + 128 + lane * 4);
            if (mask_at(mask_b, tok)) {
                acc0.x += v0.x * ib; acc0.y += v0.y * ib;
                acc0.z += v0.z * ib; acc0.w += v0.w * ib;
                acc1.x += v1.x * ib; acc1.y += v1.y * ib;
                acc1.z += v1.z * ib; acc1.w += v1.w * ib;
            }
        }
        *(float4*)&s[wid][lane * 4] = acc0;
        *(float4*)&s[wid][128 + lane * 4] = acc1;
        __syncthreads();
        int t = threadIdx.x;
        float sum = 0.f;
#pragma unroll
        for (int w = 0; w < 8; w++) sum += s[w][t];
        g_sb_part[chunk][b][t] = sum;
    }
}

__global__ void k_sb_reduce() {
    int b = blockIdx.x, t = threadIdx.x;
    float s = 0.f;
#pragma unroll
    for (int c = 0; c < 16; c++) s += g_sb_part[c][b][t];
    g_sb[b * H + t] = s;
}

// ---------------- HMMA GEMM (fp16 2-pass, scaled residual) -------------------
// BM=128: A fp16 full-K in smem (64KB). B hi+scaled-lo, 3-stage cp.async
// (3 x 32KB). 16 warps = 4 wm x 4 wn (32x32 each). smem total 160KB.
#define OFF_B0 4096   // uint4 units
#define SMEM_BYTES (10240 * 16)   // 160KB

__global__ __launch_bounds__(512, 1) void k_gemm_max() {
    extern __shared__ __align__(128) unsigned char smraw[];
    const uint32_t smb = smem_u32(smraw);

    const int b   = blockIdx.y;
    const int m0  = blockIdx.x * 128;
    const int tid = threadIdx.x, wid = tid >> 5, lane = tid & 31;
    const int wm = wid & 3, wn = wid >> 2;
    const int g = lane >> 3, ril = lane & 7;

    const uint4* gaf = (const uint4*)g_af + (size_t)(b * NTOK + m0) * 32;
    const uint4* gbh = (const uint4*)g_bh + (size_t)b * NTOK * 32;
    const uint4* gbl = (const uint4*)g_bl + (size_t)b * NTOK * 32;

    // A: 128 rows x 32 uint4, swizzled; one cp.async group
#pragma unroll
    for (int i = 0; i < 8; i++) {
        int idx = tid + i * 512;
        int r = idx >> 5, c = idx & 31, cs = c ^ (r & 7);
        cpa16(smb + (uint32_t)(r * 32 + cs) * 16, gaf + r * 32 + c);
    }
    asm volatile("cp.async.commit_group;" ::: "memory");

    // B chunk loader: ii -> n-tile ii>>2, k-chunk ii&3, buf ii%3
    auto loadB = [&](int ii) {
        int nt = ii >> 2, kc = ii & 3, buf = ii % 3;
        uint32_t base = smb + (uint32_t)(OFF_B0 + buf * 2048) * 16;
#pragma unroll
        for (int i = 0; i < 2; i++) {
            int idx = tid + i * 512;
            int n = idx >> 3, c = idx & 7, cs = c ^ (n & 7);
            size_t gi = (size_t)(nt * 128 + n) * 32 + kc * 8 + c;
            cpa16(base + (uint32_t)(n * 8 + cs) * 16, gbh + gi);
            cpa16(base + (uint32_t)(1024 + n * 8 + cs) * 16, gbl + gi);
        }
        asm volatile("cp.async.commit_group;" ::: "memory");
    };
    loadB(0);
    loadB(1);

    float pm[2][2];
    pm[0][0] = pm[0][1] = pm[1][0] = pm[1][1] = -CUDART_INF_F;
    float accH[2][4][4], accL[2][4][4];

    // ping-pong fragment buffers
    uint32_t fa[2][2][4], fbh[2][2][4], fbl[2][2][4];

    auto ldfrags = [&](int kc, int ks, int pp, int buf) {
#pragma unroll
        for (int mt = 0; mt < 2; mt++) {
            int r = wm * 32 + mt * 16 + ((g & 1) << 3) + ril;
            int c = kc * 8 + ks * 2 + (g >> 1);
            int cs = c ^ (r & 7);
            ldsm4(smb + (uint32_t)(r * 32 + cs) * 16, fa[pp][mt]);
        }
#pragma unroll
        for (int np = 0; np < 2; np++) {
            int r = wn * 32 + np * 16 + ((g & 1) << 3) + ril;
            int c = ks * 2 + (g >> 1);
            int cs = c ^ (r & 7);
            uint32_t base = (uint32_t)(OFF_B0 + buf * 2048 + r * 8 + cs);
            ldsm4(smb + base * 16, fbh[pp][np]);
            ldsm4(smb + (base + 1024) * 16, fbl[pp][np]);
        }
    };

    for (int it = 0; it < 32; it++) {
        int kc = it & 3, buf = it % 3;
        if (it < 31) {
            asm volatile("cp.async.wait_group 1;" ::: "memory");
        } else {
            asm volatile("cp.async.wait_group 0;" ::: "memory");
        }
        __syncthreads();
        if (it <= 29) loadB(it + 2);

        if (kc == 0) {
#pragma unroll
            for (int mt = 0; mt < 2; mt++)
#pragma unroll
                for (int n = 0; n < 4; n++)
#pragma unroll
                    for (int q = 0; q < 4; q++) {
                        accH[mt][n][q] = 0.f;
                        accL[mt][n][q] = 0.f;
                    }
        }

        ldfrags(kc, 0, 0, buf);
#pragma unroll
        for (int ks = 0; ks < 4; ks++) {
            int cur = ks & 1;
            if (ks < 3) ldfrags(kc, ks + 1, cur ^ 1, buf);
            // B x4 frags: [0]={n0-7,kLo} [1]={n8-15,kLo} [2]={n0-7,kHi} [3]={n8-15,kHi}
#pragma unroll
            for (int mt = 0; mt < 2; mt++)
#pragma unroll
                for (int np = 0; np < 2; np++)
#pragma unroll
                    for (int sub = 0; sub < 2; sub++) {
                        mma16816h(accH[mt][np * 2 + sub], fa[cur][mt],
                                  fbh[cur][np][sub], fbh[cur][np][sub + 2]);
                        mma16816h(accL[mt][np * 2 + sub], fa[cur][mt],
                                  fbl[cur][np][sub], fbl[cur][np][sub + 2]);
                    }
        }

        if (kc == 3) {
#pragma unroll
            for (int mt = 0; mt < 2; mt++)
#pragma unroll
                for (int n = 0; n < 4; n++) {
                    float v0 = accH[mt][n][0] + accL[mt][n][0] * (1.0f / RSCALE);
                    float v1 = accH[mt][n][1] + accL[mt][n][1] * (1.0f / RSCALE);
                    float v2 = accH[mt][n][2] + accL[mt][n][2] * (1.0f / RSCALE);
                    float v3 = accH[mt][n][3] + accL[mt][n][3] * (1.0f / RSCALE);
                    pm[mt][0] = fmaxf(pm[mt][0], fmaxf(v0, v1));
                    pm[mt][1] = fmaxf(pm[mt][1], fmaxf(v2, v3));
                }
        }
    }

    // cross-lane + cross-warp max: 128 rows x 4 wn
    __syncthreads();
    float* mred = (float*)smraw;
#pragma unroll
    for (int mt = 0; mt < 2; mt++)
#pragma unroll
        for (int hf = 0; hf < 2; hf++) {
            float v = pm[mt][hf];
            v = fmaxf(v, __shfl_xor_sync(0xffffffffu, v, 1));
            v = fmaxf(v, __shfl_xor_sync(0xffffffffu, v, 2));
            if ((lane & 3) == 0)
                mred[(wm * 32 + mt * 16 + hf * 8 + (lane >> 2)) * 4 + wn] = v;
        }
    __syncthreads();
    if (tid < 128) {
        float v = fmaxf(fmaxf(mred[tid * 4], mred[tid * 4 + 1]),
                        fmaxf(mred[tid * 4 + 2], mred[tid * 4 + 3]));
        int row = b * NTOK + m0 + tid;
        g_max[row] = v * g_inva[row];
    }
}

// ---------------- final: mean + MLP logit + softmax + aggregation ------------
__global__ void k_final(const float* __restrict__ seq_a,
                        const void* __restrict__ mask_a,
                        const float* __restrict__ w1, const float* __restrict__ b1,
                        const float* __restrict__ w2, const float* __restrict__ b2,
                        float* __restrict__ out) {
    int br = blockIdx.x;
    int t  = threadIdx.x;
    int b  = br >> 4;
    int wid = t >> 5, lane = t & 31;
    __shared__ float wrd[64], mn[64], mx[64], feat[128], attn[64], red[256], sbs[H];

    if (t < 64) {
        int tok = br * RVL + t;
        wrd[t] = g_word[tok];
        mx[t]  = g_max[tok];
    }
    sbs[t] = g_sb[b * H + t];
    __syncthreads();

    // masked mean: mn[l] = inva_l * (a_l . sb) / denom
    {
        float dnm = g_denom[b];
        float4 sb0 = *(float4*)&sbs[lane * 4];
        float4 sb1 = *(float4*)&sbs[128 + lane * 4];
#pragma unroll
        for (int i = 0; i < 8; i++) {
            int l = wid * 8 + i;
            int tok = br * RVL + l;
            const float4* pa = (const float4*)(seq_a + (size_t)tok * H);
            float4 v0 = pa[lane], v1 = pa[lane + 32];
            float ds = dot4(v0, sb0) + dot4(v1, sb1);
#pragma unroll
            for (int off = 16; off > 0; off >>= 1)
                ds += __shfl_xor_sync(0xffffffffu, ds, off);
            if (lane == 0) mn[l] = g_inva[tok] * ds / dnm;
        }
    }
    __syncthreads();

    if (t < 128) {
        int l = t >> 1;
        feat[t] = ((t & 1) ? mx[l] : mn[l]) * wrd[l];
    }
    __syncthreads();

    float acc = b1[t];
#pragma unroll 4
    for (int f = 0; f < 128; f++) acc += feat[f] * w1[f * HID + t];
    red[t] = tanhf(acc) * w2[t];
    __syncthreads();
    for (int s = 128; s > 0; s >>= 1) {
        if (t < s) red[t] += red[t + s];
        __syncthreads();
    }
    if (t == 0) out[br] = red[0] + b2[0];

    if (t == 0) {
        float m = -CUDART_INF_F;
        for (int l = 0; l < 64; l++) {
            float s = mask_at(mask_a, br * RVL + l) ? wrd[l] : NEGV;
            attn[l] = s;
            if (s > m) m = s;
        }
        float ssum = 0.f;
        for (int l = 0; l < 64; l++) {
            float e = expf(attn[l] - m);
            attn[l] = e;
            ssum += e;
        }
        float inv = 1.0f / ssum;
        for (int l = 0; l < 64; l++) attn[l] *= inv;
    }
    __syncthreads();

    const float* A = seq_a + (size_t)br * RVL * H;
    float agg = 0.f;
#pragma unroll 8
    for (int l = 0; l < 64; l++) agg += attn[l] * A[(size_t)l * H + t];
    out[BZ * RVN + br * H + t] = agg;
}

// ---------------- launch ------------------------------------------------------
extern "C" void kernel_launch(void* const* d_in, const int* in_sizes, int n_in,
                              void* d_out, int out_size) {
    const float* seq_a = (const float*)d_in[0];
    const float* seq_b = (const float*)d_in[1];
    const void*  mask_a = d_in[2];
    const void*  mask_b = d_in[3];
    const float* w_word = (const float*)d_in[4];
    const float* b_word = (const float*)d_in[5];
    const float* w1 = (const float*)d_in[6];
    const float* b1 = (const float*)d_in[7];
    const float* w2 = (const float*)d_in[8];
    const float* b2 = (const float*)d_in[9];
    float* out = (float*)d_out;

    cudaFuncSetAttribute(k_gemm_max, cudaFuncAttributeMaxDynamicSharedMemorySize,
                         SMEM_BYTES);

    k_detect_denom<<<1, 1024>>>((const unsigned char*)mask_b, mask_b);
    k_prep_ab<<<1024, 256>>>(seq_a, seq_b, mask_a, mask_b, w_word, b_word);
    k_sb_reduce<<<BZ, 256>>>();
    k_gemm_max<<<dim3(8, BZ), 512, SMEM_BYTES>>>();
    k_final<<<BZ * RVN, 256>>>(seq_a, mask_a, w1, b1, w2, b2, out);
}

// round 13
// speedup vs baseline: 1.6208x; 1.0494x over previous
#include <cuda_runtime.h>
#include <cuda_fp16.h>
#include <math_constants.h>
#include <cstdint>

#define BZ   32
#define RVN  16
#define RVL  64
#define H    256
#define NTOK 1024
#define HID  256
#define EPSF 1e-8f
#define NEGV -100000000.0f
#define RSCALE 1024.0f

// ---------------- scratch ----------------------------------------------------
__device__ __align__(16) float g_invb[BZ * NTOK];
__device__ __align__(16) float g_sb_part[16][BZ][H];
__device__ __align__(16) float g_denom[BZ];
__device__ __align__(16) float g_word[BZ * NTOK];
__device__ __align__(16) float g_inva[BZ * NTOK];
__device__ __align__(16) float g_max[BZ * NTOK];
__device__ int g_mask_byte;
// fp16 operands: A plain fp16 (raw); B hi + scaled residual (pre-scaled by 1/||b||)
__device__ __align__(16) __half g_af[BZ * NTOK * H];
__device__ __align__(16) __half g_bh[BZ * NTOK * H];
__device__ __align__(16) __half g_bl[BZ * NTOK * H];

__device__ __forceinline__ bool mask_at(const void* m, int i) {
    if (g_mask_byte) return ((const unsigned char*)m)[i] != 0;
    return ((const unsigned int*)m)[i] != 0u;
}
__device__ __forceinline__ float dot4(float4 a, float4 b) {
    return a.x * b.x + a.y * b.y + a.z * b.z + a.w * b.w;
}
__device__ __forceinline__ void cvt4_a(float4 v, __half* p) {
    __half2* d = (__half2*)p;
    d[0] = __floats2half2_rn(v.x, v.y);
    d[1] = __floats2half2_rn(v.z, v.w);
}
__device__ __forceinline__ void cvt4_b(float4 v, float s, __half* hp, __half* lp) {
    float x0 = v.x * s, x1 = v.y * s, x2 = v.z * s, x3 = v.w * s;
    __half h0 = __float2half_rn(x0), h1 = __float2half_rn(x1);
    __half h2 = __float2half_rn(x2), h3 = __float2half_rn(x3);
    float r0 = (x0 - __half2float(h0)) * RSCALE;
    float r1 = (x1 - __half2float(h1)) * RSCALE;
    float r2 = (x2 - __half2float(h2)) * RSCALE;
    float r3 = (x3 - __half2float(h3)) * RSCALE;
    __half2* hd = (__half2*)hp;
    hd[0] = __halves2half2(h0, h1);
    hd[1] = __halves2half2(h2, h3);
    __half2* ld = (__half2*)lp;
    ld[0] = __floats2half2_rn(r0, r1);
    ld[1] = __floats2half2_rn(r2, r3);
}

__device__ __forceinline__ uint32_t smem_u32(const void* p) {
    uint32_t a;
    asm("{ .reg .u64 t; cvta.to.shared.u64 t, %1; cvt.u32.u64 %0, t; }"
        : "=r"(a) : "l"(p));
    return a;
}
__device__ __forceinline__ void cpa16(uint32_t dst, const void* src) {
    asm volatile("cp.async.cg.shared.global [%0], [%1], 16;" :: "r"(dst), "l"(src));
}
__device__ __forceinline__ void ldsm4(uint32_t addr, uint32_t* r) {
    asm volatile("ldmatrix.sync.aligned.m8n8.x4.shared.b16 {%0,%1,%2,%3}, [%4];"
                 : "=r"(r[0]), "=r"(r[1]), "=r"(r[2]), "=r"(r[3]) : "r"(addr));
}
__device__ __forceinline__ void mma16816h(float* c, const uint32_t* a,
                                          uint32_t b0, uint32_t b1) {
    asm volatile(
        "mma.sync.aligned.m16n8k16.row.col.f32.f16.f16.f32 "
        "{%0,%1,%2,%3}, {%4,%5,%6,%7}, {%8,%9}, {%0,%1,%2,%3};"
        : "+f"(c[0]), "+f"(c[1]), "+f"(c[2]), "+f"(c[3])
        : "r"(a[0]), "r"(a[1]), "r"(a[2]), "r"(a[3]), "r"(b0), "r"(b1));
}

// ---------------- fused mask-width detect + per-batch denom ------------------
__global__ void k_detect_denom(const unsigned char* __restrict__ mbraw,
                               const void* __restrict__ mask_b) {
    __shared__ int mbyte;
    int t = threadIdx.x;  // 1024 threads
    if (t < 32) {
        int cnt = 0;
#pragma unroll
        for (int j = 0; j < 32; j++)
            cnt += mbraw[(t * 32 + j) * 4 + 1] ? 1 : 0;
#pragma unroll
        for (int off = 16; off > 0; off >>= 1)
            cnt += __shfl_xor_sync(0xffffffffu, cnt, off);
        if (t == 0) {
            int v = (cnt > 64) ? 1 : 0;
            g_mask_byte = v;
            mbyte = v;
        }
    }
    __syncthreads();
    int b = t >> 5, lane = t & 31;
    int c = 0;
    for (int q = lane; q < NTOK; q += 32) {
        bool m = mbyte ? (((const unsigned char*)mask_b)[b * NTOK + q] != 0)
                       : (((const unsigned int*)mask_b)[b * NTOK + q] != 0u);
        c += m ? 1 : 0;
    }
#pragma unroll
    for (int off = 16; off > 0; off >>= 1)
        c += __shfl_xor_sync(0xffffffffu, c, off);
    if (lane == 0) g_denom[b] = fmaxf((float)c, 1.0f);
}

// ---------------- fused prep: A blocks (0..511) + B blocks (512..1023) -------
__global__ void k_prep_ab(const float* __restrict__ seq_a,
                          const float* __restrict__ seq_b,
                          const void* __restrict__ mask_a,
                          const void* __restrict__ mask_b,
                          const float* __restrict__ w_word,
                          const float* __restrict__ b_word) {
    __shared__ float s[8][H];
    int bx = blockIdx.x;
    int wid = threadIdx.x >> 5, lane = threadIdx.x & 31;

    if (bx < 512) {  // ---- A: fp16 convert + word + inva ----
        int tok0 = bx * 64;
        const float4* pw = (const float4*)w_word;
        float4 w0 = pw[lane], w1v = pw[lane + 32];
        float bw = b_word[0];
#pragma unroll
        for (int i = 0; i < 8; i++) {
            int tok = tok0 + wid * 8 + i;
            const float4* pa = (const float4*)(seq_a + (size_t)tok * H);
            float4 v0 = pa[lane], v1 = pa[lane + 32];
            float ss = dot4(v0, v0) + dot4(v1, v1);
            float dw = dot4(v0, w0) + dot4(v1, w1v);
#pragma unroll
            for (int off = 16; off > 0; off >>= 1) {
                ss += __shfl_xor_sync(0xffffffffu, ss, off);
                dw += __shfl_xor_sync(0xffffffffu, dw, off);
            }
            if (lane == 0) {
                float ma = mask_at(mask_a, tok) ? 1.0f : 0.0f;
                g_word[tok] = (dw + bw) * ma;
                g_inva[tok] = 1.0f / (sqrtf(ss) + EPSF);
            }
            size_t base = (size_t)tok * H;
            cvt4_a(v0, g_af + base + lane * 4);
            cvt4_a(v1, g_af + base + 128 + lane * 4);
        }
    } else {  // ---- B: normalize, split, masked partial sums ----
        int bi = bx - 512;
        int tok0 = bi * 64;
        int b = tok0 >> 10;
        int chunk = bi & 15;
        float4 acc0 = {0.f, 0.f, 0.f, 0.f}, acc1 = {0.f, 0.f, 0.f, 0.f};
#pragma unroll
        for (int i = 0; i < 8; i++) {
            int tok = tok0 + wid * 8 + i;
            const float4* p = (const float4*)(seq_b + (size_t)tok * H);
            float4 v0 = p[lane], v1 = p[lane + 32];
            float ss = dot4(v0, v0) + dot4(v1, v1);
#pragma unroll
            for (int off = 16; off > 0; off >>= 1)
                ss += __shfl_xor_sync(0xffffffffu, ss, off);
            float ib = 1.0f / (sqrtf(ss) + EPSF);
            if (lane == 0) g_invb[tok] = ib;
            size_t base = (size_t)tok * H;
            cvt4_b(v0, ib, g_bh + base + lane * 4, g_bl + base + lane * 4);
            cvt4_b(v1, ib, g_bh + base + 128 + lane * 4, g_bl + base + 128 + lane * 4);
            if (mask_at(mask_b, tok)) {
                acc0.x += v0.x * ib; acc0.y += v0.y * ib;
                acc0.z += v0.z * ib; acc0.w += v0.w * ib;
                acc1.x += v1.x * ib; acc1.y += v1.y * ib;
                acc1.z += v1.z * ib; acc1.w += v1.w * ib;
            }
        }
        *(float4*)&s[wid][lane * 4] = acc0;
        *(float4*)&s[wid][128 + lane * 4] = acc1;
        __syncthreads();
        int t = threadIdx.x;
        float sum = 0.f;
#pragma unroll
        for (int w = 0; w < 8; w++) sum += s[w][t];
        g_sb_part[chunk][b][t] = sum;
    }
}

// ---------------- HMMA GEMM (fp16 2-pass), 2 CTAs/SM, single wave ------------
// Block = 256 threads (8 warps, 4wm x 2wn, warp 32x32). BM=128, A full-K in
// smem (64KB). B chunks 64 n-rows x 64 k-cols (hi+lo = 16KB), 3-stage pipeline.
// smem/block 112KB -> 2 CTAs/SM -> 256 blocks in one wave.
#define OFF_B0 4096     // uint4 units
#define B_STAGE 1024    // uint4 units (16KB)
#define SMEM_BYTES ((4096 + 3 * B_STAGE) * 16)   // 114688 = 112KB

__global__ __launch_bounds__(256, 2) void k_gemm_max() {
    extern __shared__ __align__(128) unsigned char smraw[];
    const uint32_t smb = smem_u32(smraw);

    const int b   = blockIdx.y;
    const int m0  = blockIdx.x * 128;
    const int tid = threadIdx.x, wid = tid >> 5, lane = tid & 31;
    const int wm = wid & 3, wn = wid >> 2;
    const int g = lane >> 3, ril = lane & 7;

    const uint4* gaf = (const uint4*)g_af + (size_t)(b * NTOK + m0) * 32;
    const uint4* gbh = (const uint4*)g_bh + (size_t)b * NTOK * 32;
    const uint4* gbl = (const uint4*)g_bl + (size_t)b * NTOK * 32;

    // A: 128 rows x 32 uint4, swizzled; one cp.async group
#pragma unroll
    for (int i = 0; i < 16; i++) {
        int idx = tid + i * 256;
        int r = idx >> 5, c = idx & 31, cs = c ^ (r & 7);
        cpa16(smb + (uint32_t)(r * 32 + cs) * 16, gaf + r * 32 + c);
    }
    asm volatile("cp.async.commit_group;" ::: "memory");

    // B chunk loader: ii -> n-chunk ii>>2 (64 rows), k-chunk ii&3 (64 cols)
    auto loadB = [&](int ii) {
        int nt = ii >> 2, kc = ii & 3, buf = ii % 3;
        uint32_t base = smb + (uint32_t)(OFF_B0 + buf * B_STAGE) * 16;
#pragma unroll
        for (int i = 0; i < 2; i++) {
            int idx = tid + i * 256;
            int n = idx >> 3, c = idx & 7, cs = c ^ (n & 7);
            size_t gi = (size_t)(nt * 64 + n) * 32 + kc * 8 + c;
            cpa16(base + (uint32_t)(n * 8 + cs) * 16, gbh + gi);
            cpa16(base + (uint32_t)(512 + n * 8 + cs) * 16, gbl + gi);
        }
        asm volatile("cp.async.commit_group;" ::: "memory");
    };
    loadB(0);
    loadB(1);

    float pm[2][2];
    pm[0][0] = pm[0][1] = pm[1][0] = pm[1][1] = -CUDART_INF_F;
    float accH[2][4][4], accL[2][4][4];

    // ping-pong fragment buffers
    uint32_t fa[2][2][4], fbh[2][2][4], fbl[2][2][4];

    auto ldfrags = [&](int kc, int ks, int pp, int buf) {
#pragma unroll
        for (int mt = 0; mt < 2; mt++) {
            int r = wm * 32 + mt * 16 + ((g & 1) << 3) + ril;
            int c = kc * 8 + ks * 2 + (g >> 1);
            int cs = c ^ (r & 7);
            ldsm4(smb + (uint32_t)(r * 32 + cs) * 16, fa[pp][mt]);
        }
#pragma unroll
        for (int np = 0; np < 2; np++) {
            int r = wn * 32 + np * 16 + ((g & 1) << 3) + ril;  // row in 64-chunk
            int c = ks * 2 + (g >> 1);
            int cs = c ^ (r & 7);
            uint32_t base = (uint32_t)(OFF_B0 + buf * B_STAGE + r * 8 + cs);
            ldsm4(smb + base * 16, fbh[pp][np]);
            ldsm4(smb + (base + 512) * 16, fbl[pp][np]);
        }
    };

    for (int ii = 0; ii < 64; ii++) {
        int kc = ii & 3, buf = ii % 3;
        if (ii < 63) {
            asm volatile("cp.async.wait_group 1;" ::: "memory");
        } else {
            asm volatile("cp.async.wait_group 0;" ::: "memory");
        }
        __syncthreads();
        if (ii <= 61) loadB(ii + 2);

        if (kc == 0) {
#pragma unroll
            for (int mt = 0; mt < 2; mt++)
#pragma unroll
                for (int n = 0; n < 4; n++)
#pragma unroll
                    for (int q = 0; q < 4; q++) {
                        accH[mt][n][q] = 0.f;
                        accL[mt][n][q] = 0.f;
                    }
        }

        ldfrags(kc, 0, 0, buf);
#pragma unroll
        for (int ks = 0; ks < 4; ks++) {
            int cur = ks & 1;
            if (ks < 3) ldfrags(kc, ks + 1, cur ^ 1, buf);
            // B x4 frags: [0]={n0-7,kLo} [1]={n8-15,kLo} [2]={n0-7,kHi} [3]={n8-15,kHi}
#pragma unroll
            for (int mt = 0; mt < 2; mt++)
#pragma unroll
                for (int np = 0; np < 2; np++)
#pragma unroll
                    for (int sub = 0; sub < 2; sub++) {
                        mma16816h(accH[mt][np * 2 + sub], fa[cur][mt],
                                  fbh[cur][np][sub], fbh[cur][np][sub + 2]);
                        mma16816h(accL[mt][np * 2 + sub], fa[cur][mt],
                                  fbl[cur][np][sub], fbl[cur][np][sub + 2]);
                    }
        }

        if (kc == 3) {
#pragma unroll
            for (int mt = 0; mt < 2; mt++)
#pragma unroll
                for (int n = 0; n < 4; n++) {
                    float v0 = accH[mt][n][0] + accL[mt][n][0] * (1.0f / RSCALE);
                    float v1 = accH[mt][n][1] + accL[mt][n][1] * (1.0f / RSCALE);
                    float v2 = accH[mt][n][2] + accL[mt][n][2] * (1.0f / RSCALE);
                    float v3 = accH[mt][n][3] + accL[mt][n][3] * (1.0f / RSCALE);
                    pm[mt][0] = fmaxf(pm[mt][0], fmaxf(v0, v1));
                    pm[mt][1] = fmaxf(pm[mt][1], fmaxf(v2, v3));
                }
        }
    }

    // cross-lane + cross-warp max: 128 rows x 2 wn
    __syncthreads();
    float* mred = (float*)smraw;
#pragma unroll
    for (int mt = 0; mt < 2; mt++)
#pragma unroll
        for (int hf = 0; hf < 2; hf++) {
            float v = pm[mt][hf];
            v = fmaxf(v, __shfl_xor_sync(0xffffffffu, v, 1));
            v = fmaxf(v, __shfl_xor_sync(0xffffffffu, v, 2));
            if ((lane & 3) == 0)
                mred[(wm * 32 + mt * 16 + hf * 8 + (lane >> 2)) * 2 + wn] = v;
        }
    __syncthreads();
    if (tid < 128) {
        float v = fmaxf(mred[tid * 2], mred[tid * 2 + 1]);
        int row = b * NTOK + m0 + tid;
        g_max[row] = v * g_inva[row];
    }
}

// ---------------- final: sb-reduce + mean + MLP + softmax + aggregation ------
__global__ void k_final(const float* __restrict__ seq_a,
                        const void* __restrict__ mask_a,
                        const float* __restrict__ w1, const float* __restrict__ b1,
                        const float* __restrict__ w2, const float* __restrict__ b2,
                        float* __restrict__ out) {
    int br = blockIdx.x;
    int t  = threadIdx.x;
    int b  = br >> 4;
    int wid = t >> 5, lane = t & 31;
    __shared__ float wrd[64], mn[64], mx[64], feat[128], attn[64], red[256], sbs[H];

    if (t < 64) {
        int tok = br * RVL + t;
        wrd[t] = g_word[tok];
        mx[t]  = g_max[tok];
    }
    {
        float s = 0.f;
#pragma unroll
        for (int c = 0; c < 16; c++) s += g_sb_part[c][b][t];
        sbs[t] = s;
    }
    __syncthreads();

    // masked mean: mn[l] = inva_l * (a_l . sb) / denom
    {
        float dnm = g_denom[b];
        float4 sb0 = *(float4*)&sbs[lane * 4];
        float4 sb1 = *(float4*)&sbs[128 + lane * 4];
#pragma unroll
        for (int i = 0; i < 8; i++) {
            int l = wid * 8 + i;
            int tok = br * RVL + l;
            const float4* pa = (const float4*)(seq_a + (size_t)tok * H);
            float4 v0 = pa[lane], v1 = pa[lane + 32];
            float ds = dot4(v0, sb0) + dot4(v1, sb1);
#pragma unroll
            for (int off = 16; off > 0; off >>= 1)
                ds += __shfl_xor_sync(0xffffffffu, ds, off);
            if (lane == 0) mn[l] = g_inva[tok] * ds / dnm;
        }
    }
    __syncthreads();

    if (t < 128) {
        int l = t >> 1;
        feat[t] = ((t & 1) ? mx[l] : mn[l]) * wrd[l];
    }
    __syncthreads();

    float acc = b1[t];
#pragma unroll 4
    for (int f = 0; f < 128; f++) acc += feat[f] * w1[f * HID + t];
    red[t] = tanhf(acc) * w2[t];
    __syncthreads();
    for (int s = 128; s > 0; s >>= 1) {
        if (t < s) red[t] += red[t + s];
        __syncthreads();
    }
    if (t == 0) out[br] = red[0] + b2[0];

    if (t == 0) {
        float m = -CUDART_INF_F;
        for (int l = 0; l < 64; l++) {
            float s = mask_at(mask_a, br * RVL + l) ? wrd[l] : NEGV;
            attn[l] = s;
            if (s > m) m = s;
        }
        float ssum = 0.f;
        for (int l = 0; l < 64; l++) {
            float e = expf(attn[l] - m);
            attn[l] = e;
            ssum += e;
        }
        float inv = 1.0f / ssum;
        for (int l = 0; l < 64; l++) attn[l] *= inv;
    }
    __syncthreads();

    const float* A = seq_a + (size_t)br * RVL * H;
    float agg = 0.f;
#pragma unroll 8
    for (int l = 0; l < 64; l++) agg += attn[l] * A[(size_t)l * H + t];
    out[BZ * RVN + br * H + t] = agg;
}

// ---------------- launch ------------------------------------------------------
extern "C" void kernel_launch(void* const* d_in, const int* in_sizes, int n_in,
                              void* d_out, int out_size) {
    const float* seq_a = (const float*)d_in[0];
    const float* seq_b = (const float*)d_in[1];
    const void*  mask_a = d_in[2];
    const void*  mask_b = d_in[3];
    const float* w_word = (const float*)d_in[4];
    const float* b_word = (const float*)d_in[5];
    const float* w1 = (const float*)d_in[6];
    const float* b1 = (const float*)d_in[7];
    const float* w2 = (const float*)d_in[8];
    const float* b2 = (const float*)d_in[9];
    float* out = (float*)d_out;

    cudaFuncSetAttribute(k_gemm_max, cudaFuncAttributeMaxDynamicSharedMemorySize,
                         SMEM_BYTES);

    k_detect_denom<<<1, 1024>>>((const unsigned char*)mask_b, mask_b);
    k_prep_ab<<<1024, 256>>>(seq_a, seq_b, mask_a, mask_b, w_word, b_word);
    k_gemm_max<<<dim3(8, BZ), 256, SMEM_BYTES>>>();
    k_final<<<BZ * RVN, 256>>>(seq_a, mask_a, w1, b1, w2, b2, out);
}